// round 2
// baseline (speedup 1.0000x reference)
#include <cuda_runtime.h>
#include <math.h>
#include <mma.h>

using namespace nvcuda;

static constexpr int B_  = 4;
static constexpr int L_  = 2048;
static constexpr int HID = 256;   // hidden after input proj
static constexpr int DI  = 512;   // d_inner
static constexpr int NS  = 16;    // d_state
static constexpr int RK  = 16;    // dt_rank
static constexpr int NCH = 64;    // chunks
static constexpr int LC  = 32;    // chunk length (NCH*LC == L_)
static constexpr int BL  = B_ * L_;   // 8192

// ---------------- scratch (device globals; no allocations allowed) ----------------
__device__ __align__(256) float g_h  [BL * HID];            // input-proj output
__device__ __align__(256) float g_xz [2 * BL * 2 * DI];     // per-dir xz (xi | z)
__device__ __align__(256) float g_u  [2 * BL * DI];         // conv+silu output
__device__ __align__(256) float g_dbc[2 * BL * 48];         // x-proj output (dt_lr|B|C)
__device__ __align__(256) float g_dt [2 * BL * DI];         // softplus dt
__device__ __align__(256) float g_S  [2 * NCH * B_ * DI * NS];
__device__ __align__(256) float g_P  [2 * NCH * B_ * DI * NS];
__device__ __align__(256) float g_Kc [2 * NCH * B_ * DI * NS];
__device__ __align__(256) float g_al [2 * NCH * B_ * DI];
__device__ __align__(256) float g_pool[2 * B_ * DI];
__device__ __align__(256) float g_embd[B_ * 2 * HID];

// =================== TF32 tensor-core GEMM (3xTF32 split for fp32 accuracy) ====
// C[M,N] = A[M,K] @ W[N,K]^T (+bias).  M % 128 == 0, K % 32 == 0, N arbitrary.
// Block tile 128x128x32; 256 threads = 8 warps in 2(m) x 4(n); warp tile 64x32.
// Each float is split a = hi + lo (both tf32-representable); the product uses
// hi*hi + hi*lo + lo*hi, giving ~2^-22 relative error (fp32-class).

static constexpr int BKs = 32;
static constexpr int LDA = BKs + 4;           // 36, padded smem stride
static constexpr int TILE_F = 128 * LDA;      // floats per tile (4608)
static constexpr int SMEM_FLOATS = 4 * TILE_F;  // As_hi, As_lo, Bs_hi, Bs_lo
static constexpr int LDC = 132;               // epilogue stride

__device__ __forceinline__ void split_tf32(float v, float& hi, float& lo) {
    hi = wmma::__float_to_tf32(v);
    lo = wmma::__float_to_tf32(v - hi);
}

__global__ void __launch_bounds__(256)
mma_gemm_kernel(const float* __restrict__ A, long sA,
                const float* __restrict__ Bw, long sB,
                float* __restrict__ C, long sC,
                const float* __restrict__ bias,
                int M, int N, int K)
{
    extern __shared__ float smem[];
    float* As_hi = smem;
    float* As_lo = smem + TILE_F;
    float* Bs_hi = smem + 2 * TILE_F;
    float* Bs_lo = smem + 3 * TILE_F;

    const int t = threadIdx.x;
    const int wid = t >> 5;
    const int wm = wid & 1;        // 0..1  (64-row slab)
    const int wn = wid >> 1;       // 0..3  (32-col slab)
    const long m0 = (long)blockIdx.y * 128;
    const int  n0 = blockIdx.x * 128;
    A  += (long)blockIdx.z * sA;
    Bw += (long)blockIdx.z * sB;
    C  += (long)blockIdx.z * sC;

    // global-load mapping: thread -> (row = t/2, 16-col half = t%2)
    const int lr = t >> 1;
    const int lc = (t & 1) * 16;
    const float* Ap = A + (m0 + lr) * (long)K + lc;
    const int bn = n0 + lr;
    const float* Bp = Bw + (long)bn * K + lc;
    const bool bvalid = bn < N;

    wmma::fragment<wmma::accumulator, 16, 16, 8, float> acc[4][2];
#pragma unroll
    for (int i = 0; i < 4; i++)
#pragma unroll
        for (int j = 0; j < 2; j++) wmma::fill_fragment(acc[i][j], 0.f);

    for (int k0 = 0; k0 < K; k0 += BKs) {
        // ---- load + split A tile ----
#pragma unroll
        for (int q = 0; q < 4; q++) {
            float4 v = *(const float4*)(Ap + k0 + q * 4);
            float h0, l0, h1, l1, h2, l2, h3, l3;
            split_tf32(v.x, h0, l0); split_tf32(v.y, h1, l1);
            split_tf32(v.z, h2, l2); split_tf32(v.w, h3, l3);
            int off = lr * LDA + lc + q * 4;
            As_hi[off + 0] = h0; As_hi[off + 1] = h1; As_hi[off + 2] = h2; As_hi[off + 3] = h3;
            As_lo[off + 0] = l0; As_lo[off + 1] = l1; As_lo[off + 2] = l2; As_lo[off + 3] = l3;
        }
        // ---- load + split B tile (zero-fill past N) ----
#pragma unroll
        for (int q = 0; q < 4; q++) {
            float4 v = bvalid ? *(const float4*)(Bp + k0 + q * 4)
                              : make_float4(0.f, 0.f, 0.f, 0.f);
            float h0, l0, h1, l1, h2, l2, h3, l3;
            split_tf32(v.x, h0, l0); split_tf32(v.y, h1, l1);
            split_tf32(v.z, h2, l2); split_tf32(v.w, h3, l3);
            int off = lr * LDA + lc + q * 4;
            Bs_hi[off + 0] = h0; Bs_hi[off + 1] = h1; Bs_hi[off + 2] = h2; Bs_hi[off + 3] = h3;
            Bs_lo[off + 0] = l0; Bs_lo[off + 1] = l1; Bs_lo[off + 2] = l2; Bs_lo[off + 3] = l3;
        }
        __syncthreads();

#pragma unroll
        for (int kk = 0; kk < BKs; kk += 8) {
            wmma::fragment<wmma::matrix_a, 16, 16, 8, wmma::precision::tf32, wmma::row_major> ah[4], al[4];
            wmma::fragment<wmma::matrix_b, 16, 16, 8, wmma::precision::tf32, wmma::col_major> bh[2], blo[2];
#pragma unroll
            for (int i = 0; i < 4; i++) {
                int r = wm * 64 + i * 16;
                wmma::load_matrix_sync(ah[i], As_hi + r * LDA + kk, LDA);
                wmma::load_matrix_sync(al[i], As_lo + r * LDA + kk, LDA);
            }
#pragma unroll
            for (int j = 0; j < 2; j++) {
                int c = wn * 32 + j * 16;
                wmma::load_matrix_sync(bh[j],  Bs_hi + c * LDA + kk, LDA);
                wmma::load_matrix_sync(blo[j], Bs_lo + c * LDA + kk, LDA);
            }
#pragma unroll
            for (int i = 0; i < 4; i++)
#pragma unroll
                for (int j = 0; j < 2; j++) {
                    wmma::mma_sync(acc[i][j], al[i], bh[j],  acc[i][j]);
                    wmma::mma_sync(acc[i][j], ah[i], blo[j], acc[i][j]);
                    wmma::mma_sync(acc[i][j], ah[i], bh[j],  acc[i][j]);
                }
        }
        __syncthreads();
    }

    // ---- epilogue: frags -> smem -> global (handles bias + N guard) ----
    float* Cs = smem;   // 128 x LDC floats (fits in the 4-tile buffer)
#pragma unroll
    for (int i = 0; i < 4; i++)
#pragma unroll
        for (int j = 0; j < 2; j++)
            wmma::store_matrix_sync(Cs + (wm * 64 + i * 16) * LDC + wn * 32 + j * 16,
                                    acc[i][j], LDC, wmma::mem_row_major);
    __syncthreads();

    for (int e = t; e < 128 * 128; e += 256) {
        int r = e >> 7;
        int cn = e & 127;
        int n = n0 + cn;
        if (n < N) {
            float v = Cs[r * LDC + cn];
            if (bias) v += bias[n];
            C[(m0 + r) * (long)N + n] = v;
        }
    }
}

// ---------------- depthwise causal conv (dir-aware) + silu --------------------
__global__ void conv_silu_kernel(const float* __restrict__ cw, const float* __restrict__ cb)
{
    int t = blockIdx.x * blockDim.x + threadIdx.x;   // 2*B*L*DI = 2^23
    int d   = t & (DI - 1);
    int l   = (t >> 9) & (L_ - 1);
    int b   = (t >> 20) & 3;
    int dir = (t >> 22) & 1;
    const float* xi = g_xz + (size_t)dir * BL * 2 * DI;   // xi = first DI cols
    const float* w  = cw + (dir * DI + d) * 4;
    float acc = cb[dir * DI + d];
    if (dir == 0) {
#pragma unroll
        for (int k = 0; k < 4; k++) {
            int ll = l - 3 + k;
            if (ll >= 0) acc = fmaf(w[k], xi[((size_t)b * L_ + ll) * (2 * DI) + d], acc);
        }
    } else {
#pragma unroll
        for (int k = 0; k < 4; k++) {
            int ll = l + 3 - k;
            if (ll < L_) acc = fmaf(w[k], xi[((size_t)b * L_ + ll) * (2 * DI) + d], acc);
        }
    }
    float uvv = acc / (1.f + __expf(-acc));   // silu
    g_u[(size_t)dir * BL * DI + ((size_t)b * L_ + l) * DI + d] = uvv;
}

// ---------------- dt = softplus(dt_lr @ dt_w^T + dt_b) (K=16 matvec fused) ----
__global__ void dt_kernel(const float* __restrict__ dt_w, const float* __restrict__ dt_b)
{
    int t = blockIdx.x * blockDim.x + threadIdx.x;
    int d   = t & (DI - 1);
    int l   = (t >> 9) & (L_ - 1);
    int b   = (t >> 20) & 3;
    int dir = (t >> 22) & 1;
    const float* row = g_dbc + (size_t)dir * BL * 48 + ((size_t)b * L_ + l) * 48;
    const float* w   = dt_w + (size_t)(dir * DI + d) * RK;
    float s = dt_b[dir * DI + d];
#pragma unroll
    for (int r = 0; r < RK; r++) s = fmaf(row[r], w[r], s);
    float dt = (s > 15.f) ? s : log1pf(__expf(s));
    g_dt[(size_t)dir * BL * DI + ((size_t)b * L_ + l) * DI + d] = dt;
}

// ---------------- chunked selective scan, pass 1 ------------------------------
__global__ void __launch_bounds__(128)
scan1_kernel(const float* __restrict__ A_log, const float* __restrict__ Dp)
{
    int bid = blockIdx.x;                 // 2048 = 2*4*64*4
    int dq  = bid & 3;
    int c   = (bid >> 2) & (NCH - 1);
    int b   = (bid >> 8) & 3;
    int dir = bid >> 10;
    int d   = dq * 128 + threadIdx.x;

    const float* dtp = g_dt  + (size_t)dir * BL * DI;
    const float* up  = g_u   + (size_t)dir * BL * DI;
    const float* zp  = g_xz  + (size_t)dir * BL * 2 * DI + DI;   // z half
    const float* dbp = g_dbc + (size_t)dir * BL * 48;

    float a[NS];
#pragma unroll
    for (int n = 0; n < NS; n++) a[n] = -__expf(A_log[(size_t)(dir * DI + d) * NS + n]);
    const float Dv = Dp[dir * DI + d];

    float h[NS], pp[NS], Kk[NS];
#pragma unroll
    for (int n = 0; n < NS; n++) { h[n] = 0.f; pp[n] = 1.f; Kk[n] = 0.f; }
    float accl = 0.f;

    for (int j = 0; j < LC; j++) {
        int s = c * LC + j;
        int l = dir ? (L_ - 1 - s) : s;
        size_t base = (size_t)b * L_ + l;
        float dtv = dtp[base * DI + d];
        float uv  = up [base * DI + d];
        float zv  = zp [base * 2 * DI + d];
        float gate = zv / (1.f + __expf(-zv));
        float x = dtv * uv;

        const float4* bc4 = (const float4*)(dbp + base * 48 + 16);
        float4 q0 = bc4[0], q1 = bc4[1], q2 = bc4[2], q3 = bc4[3];   // B
        float4 q4 = bc4[4], q5 = bc4[5], q6 = bc4[6], q7 = bc4[7];   // C
        float Bn[NS] = {q0.x, q0.y, q0.z, q0.w, q1.x, q1.y, q1.z, q1.w,
                        q2.x, q2.y, q2.z, q2.w, q3.x, q3.y, q3.z, q3.w};
        float Cn[NS] = {q4.x, q4.y, q4.z, q4.w, q5.x, q5.y, q5.z, q5.w,
                        q6.x, q6.y, q6.z, q6.w, q7.x, q7.y, q7.z, q7.w};

        float yl = 0.f;
#pragma unroll
        for (int n = 0; n < NS; n++) {
            float dA = __expf(dtv * a[n]);
            h[n]  = fmaf(dA, h[n], x * Bn[n]);
            pp[n] *= dA;
            yl    = fmaf(h[n], Cn[n], yl);
            Kk[n] = fmaf(gate * Cn[n], pp[n], Kk[n]);
        }
        accl = fmaf(gate, fmaf(uv, Dv, yl), accl);
    }

    size_t r = (((size_t)dir * NCH + c) * B_ + b) * DI + d;
    g_al[r] = accl;
#pragma unroll
    for (int n = 0; n < NS; n++) {
        g_S [r * NS + n] = h[n];
        g_P [r * NS + n] = pp[n];
        g_Kc[r * NS + n] = Kk[n];
    }
}

// ---------------- scan combine: 16 lanes per (dir,b,d), shuffle-reduce --------
__global__ void scan2_kernel()
{
    int t = blockIdx.x * blockDim.x + threadIdx.x;   // 65536
    int n   = t & 15;
    int idx = t >> 4;        // 0..4095 = dir*2048 + b*512 + d
    int dir = idx >> 11;
    int b   = (idx >> 9) & 3;
    int d   = idx & (DI - 1);
    float hin = 0.f, acc = 0.f;
    for (int c = 0; c < NCH; c++) {
        size_t r = (((size_t)dir * NCH + c) * B_ + b) * DI + d;
        if (n == 0) acc += g_al[r];
        acc = fmaf(hin, g_Kc[r * NS + n], acc);
        hin = fmaf(g_P[r * NS + n], hin, g_S[r * NS + n]);
    }
#pragma unroll
    for (int o = 8; o; o >>= 1) acc += __shfl_down_sync(0xffffffffu, acc, o, 16);
    if (n == 0) g_pool[idx] = acc;
}

// ---------------- head: pooled @ out_w^T (per dir) -> embd --------------------
__global__ void head1_kernel(const float* __restrict__ out_w)
{
    int idx = blockIdx.x * blockDim.x + threadIdx.x;   // B * 512 = 2048
    if (idx >= B_ * 2 * HID) return;
    int b = idx >> 9;
    int cf = idx & 511;
    int dir = cf >> 8;
    int cc = cf & (HID - 1);
    const float* pr = g_pool + dir * B_ * DI + b * DI;
    const float* wr = out_w + ((size_t)dir * HID + cc) * DI;
    float s = 0.f;
#pragma unroll 8
    for (int k = 0; k < DI; k++) s = fmaf(pr[k], wr[k], s);
    g_embd[b * 512 + cf] = s * (1.f / (float)L_);
}

// ---------------- head: embd @ op_w^T + op_b ----------------------------------
__global__ void head2_kernel(const float* __restrict__ op_w, const float* __restrict__ op_b,
                             float* __restrict__ out)
{
    int idx = blockIdx.x * blockDim.x + threadIdx.x;   // B * 256 = 1024
    if (idx >= B_ * HID) return;
    int b = idx >> 8;
    int m = idx & (HID - 1);
    const float* e = g_embd + b * 512;
    const float* w = op_w + (size_t)m * 512;
    float s = op_b[m];
#pragma unroll 8
    for (int c = 0; c < 512; c++) s = fmaf(e[c], w[c], s);
    out[b * HID + m] = s;
}

// ------------------------------------------------------------------------------
extern "C" void kernel_launch(void* const* d_in, const int* in_sizes, int n_in,
                              void* d_out, int out_size)
{
    const float* x      = (const float*)d_in[0];
    const float* ip_w   = (const float*)d_in[1];
    const float* ip_b   = (const float*)d_in[2];
    const float* in_w   = (const float*)d_in[3];
    const float* conv_w = (const float*)d_in[4];
    const float* conv_b = (const float*)d_in[5];
    const float* xproj_w= (const float*)d_in[6];
    const float* dt_w   = (const float*)d_in[7];
    const float* dt_b   = (const float*)d_in[8];
    const float* A_log  = (const float*)d_in[9];
    const float* Dp     = (const float*)d_in[10];
    const float* out_w  = (const float*)d_in[11];
    const float* op_w   = (const float*)d_in[12];
    const float* op_b   = (const float*)d_in[13];
    float* out = (float*)d_out;

    float *ph, *pxz, *pu, *pdbc;
    cudaGetSymbolAddress((void**)&ph,   g_h);
    cudaGetSymbolAddress((void**)&pxz,  g_xz);
    cudaGetSymbolAddress((void**)&pu,   g_u);
    cudaGetSymbolAddress((void**)&pdbc, g_dbc);

    static bool attr_done = false;
    if (!attr_done) {
        cudaFuncSetAttribute(mma_gemm_kernel,
                             cudaFuncAttributeMaxDynamicSharedMemorySize,
                             SMEM_FLOATS * (int)sizeof(float));
        attr_done = true;
    }
    const size_t shmem = SMEM_FLOATS * sizeof(float);
    dim3 blk(256);

    // 1) h = x @ ip_w^T + ip_b            [8192,512]x[256,512] -> [8192,256]
    mma_gemm_kernel<<<dim3(HID / 128, BL / 128, 1), blk, shmem>>>(
        x, 0, ip_w, 0, ph, 0, ip_b, BL, HID, 512);
    // 2) xz_dir = h @ in_w[dir]^T          [8192,256]x[1024,256] -> [8192,1024] x2
    mma_gemm_kernel<<<dim3(1024 / 128, BL / 128, 2), blk, shmem>>>(
        ph, 0, in_w, (long)1024 * HID, pxz, (long)BL * 1024, nullptr, BL, 1024, HID);
    // 3) u = silu(depthwise causal conv(xi) + cb), dir-aware time orientation
    conv_silu_kernel<<<(2 * BL * DI) / 256, 256>>>(conv_w, conv_b);
    // 4) dbc = u @ xproj_w[dir]^T          [8192,512]x[48,512] -> [8192,48] x2
    mma_gemm_kernel<<<dim3(1, BL / 128, 2), blk, shmem>>>(
        pu, (long)BL * DI, xproj_w, (long)48 * 512, pdbc, (long)BL * 48, nullptr, BL, 48, 512);
    // 5) dt = softplus(dt_lr @ dt_w^T + dt_b)
    dt_kernel<<<(2 * BL * DI) / 256, 256>>>(dt_w, dt_b);
    // 6) chunked scan pass 1 (both dirs, fused gating + pooling terms)
    scan1_kernel<<<2048, 128>>>(A_log, Dp);
    // 7) chunk combine -> pooled sums (16 lanes per channel, shuffle reduce)
    scan2_kernel<<<256, 256>>>();
    // 8) pooled @ out_w^T (mean folded), concat dirs -> embd
    head1_kernel<<<8, 256>>>(out_w);
    // 9) embd @ op_w^T + op_b -> out
    head2_kernel<<<4, 256>>>(op_w, op_b, out);
}

// round 3
// speedup vs baseline: 1.2940x; 1.2940x over previous
#include <cuda_runtime.h>
#include <math.h>
#include <mma.h>

using namespace nvcuda;

static constexpr int B_  = 4;
static constexpr int L_  = 2048;
static constexpr int HID = 256;   // hidden after input proj
static constexpr int DI  = 512;   // d_inner
static constexpr int NS  = 16;    // d_state
static constexpr int RK  = 16;    // dt_rank
static constexpr int NCH = 64;    // chunks
static constexpr int LC  = 32;    // chunk length (NCH*LC == L_)
static constexpr int BL  = B_ * L_;   // 8192

// ---------------- scratch (device globals; no allocations allowed) -------------
__device__ __align__(256) float g_h  [BL * HID];            // input-proj output
__device__ __align__(256) float g_xz [2 * BL * 2 * DI];     // per-dir xz (xi | z)
__device__ __align__(256) float g_u  [2 * BL * DI];         // conv+silu output
__device__ __align__(256) float g_dbc[2 * BL * 48];         // x-proj output (dt_lr|B|C)
__device__ __align__(256) float g_S  [2 * NCH * B_ * DI * NS];
__device__ __align__(256) float g_P  [2 * NCH * B_ * DI * NS];
__device__ __align__(256) float g_Kc [2 * NCH * B_ * DI * NS];
__device__ __align__(256) float g_al [2 * NCH * B_ * DI];
__device__ __align__(256) float g_pool[2 * B_ * DI];
__device__ __align__(256) float g_embd[B_ * 2 * HID];

// =================== TF32 tensor-core GEMM (3xTF32, prefetch-pipelined) ========
// C[M,N] = A[M,K] @ W[N,K]^T (+bias).  M % 128 == 0, K % 16 == 0.
// Block tile 128 x (64*NJ) x 16; 256 threads = 8 warps in 2(m) x 4(n).
// a = hi + lo split (exact); product hi*hi + hi*lo + lo*hi -> ~2^-22 rel err.
// Register prefetch: next k-tile LDGs issue before computing the current tile.

static constexpr int LDS_ = 20;   // smem row stride (floats); %4==0 => 16B rows

__device__ __forceinline__ void split_tf32(float v, float& hi, float& lo) {
    hi = wmma::__float_to_tf32(v);
    lo = wmma::__float_to_tf32(v - hi);
}

template<int NJ, bool GUARD>
__global__ void __launch_bounds__(256)
gemm_tc(const float* __restrict__ A, long sA,
        const float* __restrict__ Bw, long sB,
        float* __restrict__ C, long sC,
        const float* __restrict__ bias,
        int M, int N, int K)
{
    constexpr int BN = 64 * NJ;
    constexpr int A_T = 128 * LDS_;            // 2560
    constexpr int B_T = BN * LDS_;
    constexpr int SM_MAIN = 2 * A_T + 2 * B_T;
    constexpr int LDCs = BN + 4;
    constexpr int SM_EPI = GUARD ? 64 * LDCs : 0;
    constexpr int SM_TOT = (SM_MAIN > SM_EPI) ? SM_MAIN : SM_EPI;
    __shared__ float sm[SM_TOT];
    float* As_hi = sm;
    float* As_lo = sm + A_T;
    float* Bs_hi = sm + 2 * A_T;
    float* Bs_lo = sm + 2 * A_T + B_T;

    const int t = threadIdx.x;
    const int wid = t >> 5;
    const int wm = wid & 1;        // 0..1  (64-row slab)
    const int wn = wid >> 1;       // 0..3  (16*NJ-col slab)
    const long m0 = (long)blockIdx.y * 128;
    const int  n0 = blockIdx.x * BN;
    A  += (long)blockIdx.z * sA;
    Bw += (long)blockIdx.z * sB;
    C  += (long)blockIdx.z * sC;

    // global-load mapping
    const int arow = t >> 1, acol = (t & 1) * 8;            // A: 2 float4/thread
    const float* Ap = A + (m0 + arow) * (long)K + acol;
    int brow, bcol;
    if (NJ == 2) { brow = t >> 1; bcol = (t & 1) * 8; }     // B: 2 float4/thread
    else         { brow = t >> 2; bcol = (t & 3) * 4; }     // B: 1 float4/thread
    const int bn = n0 + brow;
    const float* Bp = Bw + (long)bn * K + bcol;
    const bool bvalid = !GUARD || (bn < N);

    wmma::fragment<wmma::accumulator, 16, 16, 8, float> acc[4][NJ];

    // ---- bias -> accumulator init (replicated smem tile -> acc frags) ----
    if (bias) {
        if (t < BN) {
            float v = (!GUARD || (n0 + t) < N) ? bias[n0 + t] : 0.f;
#pragma unroll
            for (int r = 0; r < 16; r++) sm[r * LDCs + t] = v;
        }
        __syncthreads();
        wmma::fragment<wmma::accumulator, 16, 16, 8, float> bf;
#pragma unroll
        for (int j = 0; j < NJ; j++) {
            wmma::load_matrix_sync(bf, sm + wn * 16 * NJ + j * 16, LDCs, wmma::mem_row_major);
#pragma unroll
            for (int i = 0; i < 4; i++)
#pragma unroll
                for (int e = 0; e < bf.num_elements; e++) acc[i][j].x[e] = bf.x[e];
        }
        __syncthreads();
    } else {
#pragma unroll
        for (int i = 0; i < 4; i++)
#pragma unroll
            for (int j = 0; j < NJ; j++) wmma::fill_fragment(acc[i][j], 0.f);
    }

    // ---- prefetch k0 = 0 ----
    float4 pa0 = *(const float4*)(Ap);
    float4 pa1 = *(const float4*)(Ap + 4);
    float4 pb0, pb1;
    pb0 = bvalid ? *(const float4*)(Bp) : make_float4(0.f, 0.f, 0.f, 0.f);
    if (NJ == 2) pb1 = bvalid ? *(const float4*)(Bp + 4) : make_float4(0.f, 0.f, 0.f, 0.f);

    for (int k0 = 0; k0 < K; k0 += 16) {
        // ---- split-store current tile ----
        {
            int off = arow * LDS_ + acol;
            float h, l;
            split_tf32(pa0.x, h, l); As_hi[off + 0] = h; As_lo[off + 0] = l;
            split_tf32(pa0.y, h, l); As_hi[off + 1] = h; As_lo[off + 1] = l;
            split_tf32(pa0.z, h, l); As_hi[off + 2] = h; As_lo[off + 2] = l;
            split_tf32(pa0.w, h, l); As_hi[off + 3] = h; As_lo[off + 3] = l;
            split_tf32(pa1.x, h, l); As_hi[off + 4] = h; As_lo[off + 4] = l;
            split_tf32(pa1.y, h, l); As_hi[off + 5] = h; As_lo[off + 5] = l;
            split_tf32(pa1.z, h, l); As_hi[off + 6] = h; As_lo[off + 6] = l;
            split_tf32(pa1.w, h, l); As_hi[off + 7] = h; As_lo[off + 7] = l;
            int bo = brow * LDS_ + bcol;
            split_tf32(pb0.x, h, l); Bs_hi[bo + 0] = h; Bs_lo[bo + 0] = l;
            split_tf32(pb0.y, h, l); Bs_hi[bo + 1] = h; Bs_lo[bo + 1] = l;
            split_tf32(pb0.z, h, l); Bs_hi[bo + 2] = h; Bs_lo[bo + 2] = l;
            split_tf32(pb0.w, h, l); Bs_hi[bo + 3] = h; Bs_lo[bo + 3] = l;
            if (NJ == 2) {
                split_tf32(pb1.x, h, l); Bs_hi[bo + 4] = h; Bs_lo[bo + 4] = l;
                split_tf32(pb1.y, h, l); Bs_hi[bo + 5] = h; Bs_lo[bo + 5] = l;
                split_tf32(pb1.z, h, l); Bs_hi[bo + 6] = h; Bs_lo[bo + 6] = l;
                split_tf32(pb1.w, h, l); Bs_hi[bo + 7] = h; Bs_lo[bo + 7] = l;
            }
        }
        __syncthreads();

        // ---- issue next tile's LDGs (latency overlapped with compute) ----
        const bool more = (k0 + 16) < K;
        if (more) {
            pa0 = *(const float4*)(Ap + k0 + 16);
            pa1 = *(const float4*)(Ap + k0 + 20);
            pb0 = bvalid ? *(const float4*)(Bp + k0 + 16) : make_float4(0.f, 0.f, 0.f, 0.f);
            if (NJ == 2)
                pb1 = bvalid ? *(const float4*)(Bp + k0 + 20) : make_float4(0.f, 0.f, 0.f, 0.f);
        }

        // ---- compute ----
#pragma unroll
        for (int kk = 0; kk < 16; kk += 8) {
            wmma::fragment<wmma::matrix_a, 16, 16, 8, wmma::precision::tf32, wmma::row_major> ah[4], al[4];
            wmma::fragment<wmma::matrix_b, 16, 16, 8, wmma::precision::tf32, wmma::col_major> bh[NJ], blo[NJ];
#pragma unroll
            for (int i = 0; i < 4; i++) {
                int r = wm * 64 + i * 16;
                wmma::load_matrix_sync(ah[i], As_hi + r * LDS_ + kk, LDS_);
                wmma::load_matrix_sync(al[i], As_lo + r * LDS_ + kk, LDS_);
            }
#pragma unroll
            for (int j = 0; j < NJ; j++) {
                int c = wn * 16 * NJ + j * 16;
                wmma::load_matrix_sync(bh[j],  Bs_hi + c * LDS_ + kk, LDS_);
                wmma::load_matrix_sync(blo[j], Bs_lo + c * LDS_ + kk, LDS_);
            }
#pragma unroll
            for (int i = 0; i < 4; i++)
#pragma unroll
                for (int j = 0; j < NJ; j++) {
                    wmma::mma_sync(acc[i][j], al[i], bh[j],  acc[i][j]);
                    wmma::mma_sync(acc[i][j], ah[i], blo[j], acc[i][j]);
                    wmma::mma_sync(acc[i][j], ah[i], bh[j],  acc[i][j]);
                }
        }
        __syncthreads();
    }

    // ---- epilogue ----
    if (!GUARD) {
        // N % BN == 0 for these calls: direct fragment stores to global
#pragma unroll
        for (int i = 0; i < 4; i++)
#pragma unroll
            for (int j = 0; j < NJ; j++)
                wmma::store_matrix_sync(
                    C + (m0 + wm * 64 + i * 16) * (long)N + n0 + wn * 16 * NJ + j * 16,
                    acc[i][j], N, wmma::mem_row_major);
    } else {
        // two-pass smem round-trip with column guard
        for (int half = 0; half < 2; half++) {
            if (wm == half) {
#pragma unroll
                for (int i = 0; i < 4; i++)
#pragma unroll
                    for (int j = 0; j < NJ; j++)
                        wmma::store_matrix_sync(sm + (i * 16) * LDCs + wn * 16 * NJ + j * 16,
                                                acc[i][j], LDCs, wmma::mem_row_major);
            }
            __syncthreads();
            for (int e = t; e < 64 * BN; e += 256) {
                int r = e / BN, cn = e % BN;
                int n = n0 + cn;
                if (n < N)
                    C[(m0 + half * 64 + r) * (long)N + n] = sm[r * LDCs + cn];
            }
            __syncthreads();
        }
    }
}

// ---------------- depthwise causal conv (dir-aware) + silu --------------------
__global__ void conv_silu_kernel(const float* __restrict__ cw, const float* __restrict__ cb)
{
    int t = blockIdx.x * blockDim.x + threadIdx.x;   // 2*B*L*DI = 2^23
    int d   = t & (DI - 1);
    int l   = (t >> 9) & (L_ - 1);
    int b   = (t >> 20) & 3;
    int dir = (t >> 22) & 1;
    const float* xi = g_xz + (size_t)dir * BL * 2 * DI;   // xi = first DI cols
    const float* w  = cw + (dir * DI + d) * 4;
    float acc = cb[dir * DI + d];
    if (dir == 0) {
#pragma unroll
        for (int k = 0; k < 4; k++) {
            int ll = l - 3 + k;
            if (ll >= 0) acc = fmaf(w[k], xi[((size_t)b * L_ + ll) * (2 * DI) + d], acc);
        }
    } else {
#pragma unroll
        for (int k = 0; k < 4; k++) {
            int ll = l + 3 - k;
            if (ll < L_) acc = fmaf(w[k], xi[((size_t)b * L_ + ll) * (2 * DI) + d], acc);
        }
    }
    float uvv = acc / (1.f + __expf(-acc));   // silu
    g_u[(size_t)dir * BL * DI + ((size_t)b * L_ + l) * DI + d] = uvv;
}

// ---------------- chunked selective scan, pass 1 (dt fused inline) ------------
__global__ void __launch_bounds__(128)
scan1_kernel(const float* __restrict__ A_log, const float* __restrict__ Dp,
             const float* __restrict__ dt_w, const float* __restrict__ dt_b)
{
    int bid = blockIdx.x;                 // 2048 = 2*4*64*4
    int dq  = bid & 3;
    int c   = (bid >> 2) & (NCH - 1);
    int b   = (bid >> 8) & 3;
    int dir = bid >> 10;
    int d   = dq * 128 + threadIdx.x;

    const float* up  = g_u   + (size_t)dir * BL * DI;
    const float* zp  = g_xz  + (size_t)dir * BL * 2 * DI + DI;   // z half
    const float* dbp = g_dbc + (size_t)dir * BL * 48;

    float a[NS];
#pragma unroll
    for (int n = 0; n < NS; n++) a[n] = -__expf(A_log[(size_t)(dir * DI + d) * NS + n]);
    const float Dv = Dp[dir * DI + d];

    // dt row weights for this channel
    float wreg[RK];
    {
        const float* wr = dt_w + (size_t)(dir * DI + d) * RK;
#pragma unroll
        for (int r = 0; r < RK; r++) wreg[r] = wr[r];
    }
    const float bb = dt_b[dir * DI + d];

    float h[NS], pp[NS], Kk[NS];
#pragma unroll
    for (int n = 0; n < NS; n++) { h[n] = 0.f; pp[n] = 1.f; Kk[n] = 0.f; }
    float accl = 0.f;

    for (int j = 0; j < LC; j++) {
        int s = c * LC + j;
        int l = dir ? (L_ - 1 - s) : s;
        size_t base = (size_t)b * L_ + l;
        float uv = up[base * DI + d];
        float zv = zp[base * 2 * DI + d];
        float gate = zv / (1.f + __expf(-zv));

        const float4* rr = (const float4*)(dbp + base * 48);
        float4 p0 = rr[0], p1 = rr[1], p2 = rr[2], p3 = rr[3];   // dt_lr
        float sdt = bb;
        sdt = fmaf(p0.x, wreg[0], sdt);  sdt = fmaf(p0.y, wreg[1], sdt);
        sdt = fmaf(p0.z, wreg[2], sdt);  sdt = fmaf(p0.w, wreg[3], sdt);
        sdt = fmaf(p1.x, wreg[4], sdt);  sdt = fmaf(p1.y, wreg[5], sdt);
        sdt = fmaf(p1.z, wreg[6], sdt);  sdt = fmaf(p1.w, wreg[7], sdt);
        sdt = fmaf(p2.x, wreg[8], sdt);  sdt = fmaf(p2.y, wreg[9], sdt);
        sdt = fmaf(p2.z, wreg[10], sdt); sdt = fmaf(p2.w, wreg[11], sdt);
        sdt = fmaf(p3.x, wreg[12], sdt); sdt = fmaf(p3.y, wreg[13], sdt);
        sdt = fmaf(p3.z, wreg[14], sdt); sdt = fmaf(p3.w, wreg[15], sdt);
        float dtv = (sdt > 15.f) ? sdt : log1pf(__expf(sdt));
        float x = dtv * uv;

        float4 q0 = rr[4], q1 = rr[5], q2 = rr[6], q3 = rr[7];   // B
        float4 q4 = rr[8], q5 = rr[9], q6 = rr[10], q7 = rr[11]; // C
        float Bn[NS] = {q0.x, q0.y, q0.z, q0.w, q1.x, q1.y, q1.z, q1.w,
                        q2.x, q2.y, q2.z, q2.w, q3.x, q3.y, q3.z, q3.w};
        float Cn[NS] = {q4.x, q4.y, q4.z, q4.w, q5.x, q5.y, q5.z, q5.w,
                        q6.x, q6.y, q6.z, q6.w, q7.x, q7.y, q7.z, q7.w};

        float yl = 0.f;
#pragma unroll
        for (int n = 0; n < NS; n++) {
            float dA = __expf(dtv * a[n]);
            h[n]  = fmaf(dA, h[n], x * Bn[n]);
            pp[n] *= dA;
            yl    = fmaf(h[n], Cn[n], yl);
            Kk[n] = fmaf(gate * Cn[n], pp[n], Kk[n]);
        }
        accl = fmaf(gate, fmaf(uv, Dv, yl), accl);
    }

    size_t r = (((size_t)dir * NCH + c) * B_ + b) * DI + d;
    g_al[r] = accl;
#pragma unroll
    for (int n = 0; n < NS; n++) {
        g_S [r * NS + n] = h[n];
        g_P [r * NS + n] = pp[n];
        g_Kc[r * NS + n] = Kk[n];
    }
}

// ---------------- scan combine: 16 lanes per (dir,b,d), shuffle-reduce --------
__global__ void scan2_kernel()
{
    int t = blockIdx.x * blockDim.x + threadIdx.x;   // 65536
    int n   = t & 15;
    int idx = t >> 4;        // 0..4095 = dir*2048 + b*512 + d
    int dir = idx >> 11;
    int b   = (idx >> 9) & 3;
    int d   = idx & (DI - 1);
    float hin = 0.f, acc = 0.f;
    for (int c = 0; c < NCH; c++) {
        size_t r = (((size_t)dir * NCH + c) * B_ + b) * DI + d;
        if (n == 0) acc += g_al[r];
        acc = fmaf(hin, g_Kc[r * NS + n], acc);
        hin = fmaf(g_P[r * NS + n], hin, g_S[r * NS + n]);
    }
#pragma unroll
    for (int o = 8; o; o >>= 1) acc += __shfl_down_sync(0xffffffffu, acc, o, 16);
    if (n == 0) g_pool[idx] = acc;
}

// ---------------- head: pooled @ out_w^T (per dir) -> embd --------------------
__global__ void head1_kernel(const float* __restrict__ out_w)
{
    int idx = blockIdx.x * blockDim.x + threadIdx.x;   // B * 512 = 2048
    if (idx >= B_ * 2 * HID) return;
    int b = idx >> 9;
    int cf = idx & 511;
    int dir = cf >> 8;
    int cc = cf & (HID - 1);
    const float* pr = g_pool + dir * B_ * DI + b * DI;
    const float* wr = out_w + ((size_t)dir * HID + cc) * DI;
    float s = 0.f;
#pragma unroll 8
    for (int k = 0; k < DI; k++) s = fmaf(pr[k], wr[k], s);
    g_embd[b * 512 + cf] = s * (1.f / (float)L_);
}

// ---------------- head: embd @ op_w^T + op_b ----------------------------------
__global__ void head2_kernel(const float* __restrict__ op_w, const float* __restrict__ op_b,
                             float* __restrict__ out)
{
    int idx = blockIdx.x * blockDim.x + threadIdx.x;   // B * 256 = 1024
    if (idx >= B_ * HID) return;
    int b = idx >> 8;
    int m = idx & (HID - 1);
    const float* e = g_embd + b * 512;
    const float* w = op_w + (size_t)m * 512;
    float s = op_b[m];
#pragma unroll 8
    for (int c = 0; c < 512; c++) s = fmaf(e[c], w[c], s);
    out[b * HID + m] = s;
}

// ------------------------------------------------------------------------------
extern "C" void kernel_launch(void* const* d_in, const int* in_sizes, int n_in,
                              void* d_out, int out_size)
{
    const float* x      = (const float*)d_in[0];
    const float* ip_w   = (const float*)d_in[1];
    const float* ip_b   = (const float*)d_in[2];
    const float* in_w   = (const float*)d_in[3];
    const float* conv_w = (const float*)d_in[4];
    const float* conv_b = (const float*)d_in[5];
    const float* xproj_w= (const float*)d_in[6];
    const float* dt_w   = (const float*)d_in[7];
    const float* dt_b   = (const float*)d_in[8];
    const float* A_log  = (const float*)d_in[9];
    const float* Dp     = (const float*)d_in[10];
    const float* out_w  = (const float*)d_in[11];
    const float* op_w   = (const float*)d_in[12];
    const float* op_b   = (const float*)d_in[13];
    float* out = (float*)d_out;

    float *ph, *pxz, *pu, *pdbc;
    cudaGetSymbolAddress((void**)&ph,   g_h);
    cudaGetSymbolAddress((void**)&pxz,  g_xz);
    cudaGetSymbolAddress((void**)&pu,   g_u);
    cudaGetSymbolAddress((void**)&pdbc, g_dbc);

    dim3 blk(256);
    // 1) h = x @ ip_w^T + ip_b            [8192,512]x[256,512] -> [8192,256]
    gemm_tc<2, false><<<dim3(HID / 128, BL / 128, 1), blk>>>(
        x, 0, ip_w, 0, ph, 0, ip_b, BL, HID, 512);
    // 2) xz_dir = h @ in_w[dir]^T          [8192,256]x[1024,256] -> [8192,1024] x2
    gemm_tc<2, false><<<dim3(1024 / 128, BL / 128, 2), blk>>>(
        ph, 0, in_w, (long)1024 * HID, pxz, (long)BL * 1024, nullptr, BL, 1024, HID);
    // 3) u = silu(depthwise causal conv(xi) + cb), dir-aware time orientation
    conv_silu_kernel<<<(2 * BL * DI) / 256, 256>>>(conv_w, conv_b);
    // 4) dbc = u @ xproj_w[dir]^T          [8192,512]x[48,512] -> [8192,48] x2
    gemm_tc<1, true><<<dim3(1, BL / 128, 2), blk>>>(
        pu, (long)BL * DI, xproj_w, (long)48 * 512, pdbc, (long)BL * 48, nullptr, BL, 48, 512);
    // 5) chunked scan pass 1 (dt fused; gating + pooling terms fused)
    scan1_kernel<<<2048, 128>>>(A_log, Dp, dt_w, dt_b);
    // 6) chunk combine -> pooled sums (16 lanes per channel, shuffle reduce)
    scan2_kernel<<<256, 256>>>();
    // 7) pooled @ out_w^T (mean folded), concat dirs -> embd
    head1_kernel<<<8, 256>>>(out_w);
    // 8) embd @ op_w^T + op_b -> out
    head2_kernel<<<4, 256>>>(op_w, op_b, out);
}

// round 5
// speedup vs baseline: 1.4234x; 1.1000x over previous
#include <cuda_runtime.h>
#include <cstdint>
#include <math.h>
#include <mma.h>

using namespace nvcuda;

static constexpr int B_  = 4;
static constexpr int L_  = 2048;
static constexpr int HID = 256;   // hidden after input proj
static constexpr int DI  = 512;   // d_inner
static constexpr int NS  = 16;    // d_state
static constexpr int RK  = 16;    // dt_rank
static constexpr int NCH = 64;    // chunks
static constexpr int LC  = 32;    // chunk length (NCH*LC == L_)
static constexpr int BL  = B_ * L_;   // 8192

// ---------------- scratch (device globals; no allocations allowed) -------------
__device__ __align__(256) float g_h  [BL * HID];            // input-proj output
__device__ __align__(256) float g_xz [2 * BL * 2 * DI];     // per-dir xz (xi | z)
__device__ __align__(256) float g_u  [2 * BL * DI];         // conv+silu output
__device__ __align__(256) float g_dbc[2 * BL * 48];         // x-proj output (dt_lr|B|C)
__device__ __align__(256) float g_S  [2 * NCH * B_ * DI * NS];
__device__ __align__(256) float g_P  [2 * NCH * B_ * DI * NS];
__device__ __align__(256) float g_Kc [2 * NCH * B_ * DI * NS];
__device__ __align__(256) float g_al [2 * NCH * B_ * DI];
__device__ __align__(256) float g_pool[2 * B_ * DI];
__device__ __align__(256) float g_embd[B_ * 2 * HID];

// =================== TF32 tensor-core GEMM, cp.async 4-stage pipeline ==========
// C[M,N] = A[M,K] @ W[N,K]^T (+bias).  M % 128 == 0, K % 16 == 0.
// Block tile 128 x (64*NJ) x 16; 256 threads = 8 warps in 2(m) x 4(n).
// Raw fp32 tiles stream into a 4-stage smem ring via cp.async; the hi/lo
// 3xTF32 split (fp32-class accuracy, ~2^-22) happens per-fragment in registers.

static constexpr int LDT   = 20;   // smem row stride (floats); 80B, 16B-aligned
static constexpr int NSTG  = 4;    // pipeline stages

__device__ __forceinline__ void cp16(float* dst, const float* src, int srcbytes) {
    unsigned int d = (unsigned int)__cvta_generic_to_shared(dst);
    asm volatile("cp.async.cg.shared.global [%0], [%1], 16, %2;\n"
                 :: "r"(d), "l"(src), "r"(srcbytes));
}
__device__ __forceinline__ void cp_commit() {
    asm volatile("cp.async.commit_group;\n");
}
template<int Nleft>
__device__ __forceinline__ void cp_wait() {
    asm volatile("cp.async.wait_group %0;\n" :: "n"(Nleft));
}

template<class Frag>
__device__ __forceinline__ void split_frag(const Frag& r, Frag& hi, Frag& lo) {
#pragma unroll
    for (int e = 0; e < r.num_elements; e++) {
        float h = wmma::__float_to_tf32(r.x[e]);
        hi.x[e] = h;
        lo.x[e] = wmma::__float_to_tf32(r.x[e] - h);
    }
}

template<int NJ, bool GUARD>
__global__ void __launch_bounds__(256)
gemm_tc(const float* __restrict__ A, long sA,
        const float* __restrict__ Bw, long sB,
        float* __restrict__ C, long sC,
        const float* __restrict__ bias,
        int M, int N, int K)
{
    constexpr int BN  = 64 * NJ;
    constexpr int A_T = 128 * LDT;           // 2560 floats
    constexpr int B_T = BN * LDT;
    constexpr int STG = A_T + B_T;           // floats per stage
    constexpr int LDCs = BN + 4;
    extern __shared__ float sm[];

    const int t = threadIdx.x;
    const int wid = t >> 5;
    const int wm = wid & 1;        // 0..1  (64-row slab)
    const int wn = wid >> 1;       // 0..3  (16*NJ-col slab)
    const long m0 = (long)blockIdx.y * 128;
    const int  n0 = blockIdx.x * BN;
    A  += (long)blockIdx.z * sA;
    Bw += (long)blockIdx.z * sB;
    C  += (long)blockIdx.z * sC;

    // cp.async mapping: 16B chunk per (row, k-quad); thread -> row t>>2, kcol (t&3)*4
    const int crow = t >> 2;               // 0..63
    const int kc   = (t & 3) * 4;
    const float* Ag0 = A + (m0 + crow) * (long)K + kc;
    const float* Ag1 = Ag0 + 64 * (long)K;
    const int bn0 = n0 + crow;
    const int bn1 = n0 + crow + 64;
    const float* Bg0 = Bw + (long)(GUARD ? (bn0 < N ? bn0 : 0) : bn0) * K + kc;
    const float* Bg1 = Bw + (long)(GUARD ? (bn1 < N ? bn1 : 0) : bn1) * K + kc;
    const int bb0 = (!GUARD || bn0 < N) ? 16 : 0;
    const int bb1 = (!GUARD || bn1 < N) ? 16 : 0;

    wmma::fragment<wmma::accumulator, 16, 16, 8, float> acc[4][NJ];

    // ---- bias -> accumulator init (replicated smem tile -> acc frags) ----
    if (bias) {
        if (t < BN) {
            float v = (!GUARD || (n0 + t) < N) ? bias[n0 + t] : 0.f;
#pragma unroll
            for (int r = 0; r < 16; r++) sm[r * LDCs + t] = v;
        }
        __syncthreads();
        wmma::fragment<wmma::accumulator, 16, 16, 8, float> bf;
#pragma unroll
        for (int j = 0; j < NJ; j++) {
            wmma::load_matrix_sync(bf, sm + wn * 16 * NJ + j * 16, LDCs, wmma::mem_row_major);
#pragma unroll
            for (int i = 0; i < 4; i++)
#pragma unroll
                for (int e = 0; e < bf.num_elements; e++) acc[i][j].x[e] = bf.x[e];
        }
        __syncthreads();
    } else {
#pragma unroll
        for (int i = 0; i < 4; i++)
#pragma unroll
            for (int j = 0; j < NJ; j++) wmma::fill_fragment(acc[i][j], 0.f);
    }

    // ---- pipeline prologue: issue stages 0..NSTG-2 ----
    auto issue = [&](int s, int k) {
        float* As = sm + s * STG;
        float* Bs = As + A_T;
        cp16(As + crow * LDT + kc,        Ag0 + k, 16);
        cp16(As + (crow + 64) * LDT + kc, Ag1 + k, 16);
        cp16(Bs + crow * LDT + kc,        Bg0 + k, bb0);
        if (NJ == 2) cp16(Bs + (crow + 64) * LDT + kc, Bg1 + k, bb1);
    };
#pragma unroll
    for (int p = 0; p < NSTG - 1; p++) {
        if (p * 16 < K) issue(p, p * 16);
        cp_commit();
    }

    int s = 0;
    for (int k0 = 0; k0 < K; k0 += 16) {
        cp_wait<NSTG - 2>();
        __syncthreads();

        // issue the stage that is NSTG-1 tiles ahead (into the just-freed buffer)
        int kp = k0 + (NSTG - 1) * 16;
        int sp = s + (NSTG - 1); if (sp >= NSTG) sp -= NSTG;
        if (kp < K) issue(sp, kp);
        cp_commit();

        // compute on stage s
        float* As = sm + s * STG;
        float* Bs = As + A_T;
#pragma unroll
        for (int kk = 0; kk < 16; kk += 8) {
            wmma::fragment<wmma::matrix_a, 16, 16, 8, wmma::precision::tf32, wmma::row_major> ah[4], al[4];
            wmma::fragment<wmma::matrix_b, 16, 16, 8, wmma::precision::tf32, wmma::col_major> bh[NJ], bl[NJ];
            {
                wmma::fragment<wmma::matrix_a, 16, 16, 8, wmma::precision::tf32, wmma::row_major> raw;
#pragma unroll
                for (int i = 0; i < 4; i++) {
                    wmma::load_matrix_sync(raw, As + (wm * 64 + i * 16) * LDT + kk, LDT);
                    split_frag(raw, ah[i], al[i]);
                }
            }
            {
                wmma::fragment<wmma::matrix_b, 16, 16, 8, wmma::precision::tf32, wmma::col_major> rawb;
#pragma unroll
                for (int j = 0; j < NJ; j++) {
                    wmma::load_matrix_sync(rawb, Bs + (wn * 16 * NJ + j * 16) * LDT + kk, LDT);
                    split_frag(rawb, bh[j], bl[j]);
                }
            }
#pragma unroll
            for (int i = 0; i < 4; i++)
#pragma unroll
                for (int j = 0; j < NJ; j++) {
                    wmma::mma_sync(acc[i][j], al[i], bh[j], acc[i][j]);
                    wmma::mma_sync(acc[i][j], ah[i], bl[j], acc[i][j]);
                    wmma::mma_sync(acc[i][j], ah[i], bh[j], acc[i][j]);
                }
        }
        s++; if (s == NSTG) s = 0;
    }

    // ---- epilogue ----
    if (!GUARD) {
#pragma unroll
        for (int i = 0; i < 4; i++)
#pragma unroll
            for (int j = 0; j < NJ; j++)
                wmma::store_matrix_sync(
                    C + (m0 + wm * 64 + i * 16) * (long)N + n0 + wn * 16 * NJ + j * 16,
                    acc[i][j], N, wmma::mem_row_major);
    } else {
        __syncthreads();
        for (int half = 0; half < 2; half++) {
            if (wm == half) {
#pragma unroll
                for (int i = 0; i < 4; i++)
#pragma unroll
                    for (int j = 0; j < NJ; j++)
                        wmma::store_matrix_sync(sm + (i * 16) * LDCs + wn * 16 * NJ + j * 16,
                                                acc[i][j], LDCs, wmma::mem_row_major);
            }
            __syncthreads();
            for (int e = t; e < 64 * BN; e += 256) {
                int r = e / BN, cn = e % BN;
                int n = n0 + cn;
                if (n < N)
                    C[(m0 + half * 64 + r) * (long)N + n] = sm[r * LDCs + cn];
            }
            __syncthreads();
        }
    }
}

// ---------------- depthwise causal conv (dir-aware) + silu --------------------
__global__ void conv_silu_kernel(const float* __restrict__ cw, const float* __restrict__ cb)
{
    int t = blockIdx.x * blockDim.x + threadIdx.x;   // 2*B*L*DI = 2^23
    int d   = t & (DI - 1);
    int l   = (t >> 9) & (L_ - 1);
    int b   = (t >> 20) & 3;
    int dir = (t >> 22) & 1;
    const float* xi = g_xz + (size_t)dir * BL * 2 * DI;   // xi = first DI cols
    const float* w  = cw + (dir * DI + d) * 4;
    float acc = cb[dir * DI + d];
    if (dir == 0) {
#pragma unroll
        for (int k = 0; k < 4; k++) {
            int ll = l - 3 + k;
            if (ll >= 0) acc = fmaf(w[k], xi[((size_t)b * L_ + ll) * (2 * DI) + d], acc);
        }
    } else {
#pragma unroll
        for (int k = 0; k < 4; k++) {
            int ll = l + 3 - k;
            if (ll < L_) acc = fmaf(w[k], xi[((size_t)b * L_ + ll) * (2 * DI) + d], acc);
        }
    }
    float uvv = acc / (1.f + __expf(-acc));   // silu
    g_u[(size_t)dir * BL * DI + ((size_t)b * L_ + l) * DI + d] = uvv;
}

// ---------------- chunked selective scan, pass 1 (dt fused inline) ------------
__global__ void __launch_bounds__(128)
scan1_kernel(const float* __restrict__ A_log, const float* __restrict__ Dp,
             const float* __restrict__ dt_w, const float* __restrict__ dt_b)
{
    int bid = blockIdx.x;                 // 2048 = 2*4*64*4
    int dq  = bid & 3;
    int c   = (bid >> 2) & (NCH - 1);
    int b   = (bid >> 8) & 3;
    int dir = bid >> 10;
    int d   = dq * 128 + threadIdx.x;

    const float* up  = g_u   + (size_t)dir * BL * DI;
    const float* zp  = g_xz  + (size_t)dir * BL * 2 * DI + DI;   // z half
    const float* dbp = g_dbc + (size_t)dir * BL * 48;

    float a[NS];
#pragma unroll
    for (int n = 0; n < NS; n++) a[n] = -__expf(A_log[(size_t)(dir * DI + d) * NS + n]);
    const float Dv = Dp[dir * DI + d];

    float wreg[RK];
    {
        const float* wr = dt_w + (size_t)(dir * DI + d) * RK;
#pragma unroll
        for (int r = 0; r < RK; r++) wreg[r] = wr[r];
    }
    const float bb = dt_b[dir * DI + d];

    float h[NS], pp[NS], Kk[NS];
#pragma unroll
    for (int n = 0; n < NS; n++) { h[n] = 0.f; pp[n] = 1.f; Kk[n] = 0.f; }
    float accl = 0.f;

    for (int j = 0; j < LC; j++) {
        int s = c * LC + j;
        int l = dir ? (L_ - 1 - s) : s;
        size_t base = (size_t)b * L_ + l;
        float uv = up[base * DI + d];
        float zv = zp[base * 2 * DI + d];
        float gate = zv / (1.f + __expf(-zv));

        const float4* rr = (const float4*)(dbp + base * 48);
        float4 p0 = rr[0], p1 = rr[1], p2 = rr[2], p3 = rr[3];   // dt_lr
        float sdt = bb;
        sdt = fmaf(p0.x, wreg[0], sdt);  sdt = fmaf(p0.y, wreg[1], sdt);
        sdt = fmaf(p0.z, wreg[2], sdt);  sdt = fmaf(p0.w, wreg[3], sdt);
        sdt = fmaf(p1.x, wreg[4], sdt);  sdt = fmaf(p1.y, wreg[5], sdt);
        sdt = fmaf(p1.z, wreg[6], sdt);  sdt = fmaf(p1.w, wreg[7], sdt);
        sdt = fmaf(p2.x, wreg[8], sdt);  sdt = fmaf(p2.y, wreg[9], sdt);
        sdt = fmaf(p2.z, wreg[10], sdt); sdt = fmaf(p2.w, wreg[11], sdt);
        sdt = fmaf(p3.x, wreg[12], sdt); sdt = fmaf(p3.y, wreg[13], sdt);
        sdt = fmaf(p3.z, wreg[14], sdt); sdt = fmaf(p3.w, wreg[15], sdt);
        float dtv = (sdt > 15.f) ? sdt : log1pf(__expf(sdt));
        float x = dtv * uv;

        float4 q0 = rr[4], q1 = rr[5], q2 = rr[6], q3 = rr[7];   // B
        float4 q4 = rr[8], q5 = rr[9], q6 = rr[10], q7 = rr[11]; // C
        float Bn[NS] = {q0.x, q0.y, q0.z, q0.w, q1.x, q1.y, q1.z, q1.w,
                        q2.x, q2.y, q2.z, q2.w, q3.x, q3.y, q3.z, q3.w};
        float Cn[NS] = {q4.x, q4.y, q4.z, q4.w, q5.x, q5.y, q5.z, q5.w,
                        q6.x, q6.y, q6.z, q6.w, q7.x, q7.y, q7.z, q7.w};

        float yl = 0.f;
#pragma unroll
        for (int n = 0; n < NS; n++) {
            float dA = __expf(dtv * a[n]);
            h[n]  = fmaf(dA, h[n], x * Bn[n]);
            pp[n] *= dA;
            yl    = fmaf(h[n], Cn[n], yl);
            Kk[n] = fmaf(gate * Cn[n], pp[n], Kk[n]);
        }
        accl = fmaf(gate, fmaf(uv, Dv, yl), accl);
    }

    size_t r = (((size_t)dir * NCH + c) * B_ + b) * DI + d;
    g_al[r] = accl;
#pragma unroll
    for (int n = 0; n < NS; n++) {
        g_S [r * NS + n] = h[n];
        g_P [r * NS + n] = pp[n];
        g_Kc[r * NS + n] = Kk[n];
    }
}

// ---------------- scan combine: 16 lanes per (dir,b,d), shuffle-reduce --------
__global__ void scan2_kernel()
{
    int t = blockIdx.x * blockDim.x + threadIdx.x;   // 65536
    int n   = t & 15;
    int idx = t >> 4;        // 0..4095 = dir*2048 + b*512 + d
    int dir = idx >> 11;
    int b   = (idx >> 9) & 3;
    int d   = idx & (DI - 1);
    float hin = 0.f, acc = 0.f;
    for (int c = 0; c < NCH; c++) {
        size_t r = (((size_t)dir * NCH + c) * B_ + b) * DI + d;
        if (n == 0) acc += g_al[r];
        acc = fmaf(hin, g_Kc[r * NS + n], acc);
        hin = fmaf(g_P[r * NS + n], hin, g_S[r * NS + n]);
    }
#pragma unroll
    for (int o = 8; o; o >>= 1) acc += __shfl_down_sync(0xffffffffu, acc, o, 16);
    if (n == 0) g_pool[idx] = acc;
}

// ---------------- head: pooled @ out_w^T (per dir) -> embd --------------------
__global__ void head1_kernel(const float* __restrict__ out_w)
{
    int idx = blockIdx.x * blockDim.x + threadIdx.x;   // B * 512 = 2048
    if (idx >= B_ * 2 * HID) return;
    int b = idx >> 9;
    int cf = idx & 511;
    int dir = cf >> 8;
    int cc = cf & (HID - 1);
    const float* pr = g_pool + dir * B_ * DI + b * DI;
    const float* wr = out_w + ((size_t)dir * HID + cc) * DI;
    float s = 0.f;
#pragma unroll 8
    for (int k = 0; k < DI; k++) s = fmaf(pr[k], wr[k], s);
    g_embd[b * 512 + cf] = s * (1.f / (float)L_);
}

// ---------------- head: embd @ op_w^T + op_b ----------------------------------
__global__ void head2_kernel(const float* __restrict__ op_w, const float* __restrict__ op_b,
                             float* __restrict__ out)
{
    int idx = blockIdx.x * blockDim.x + threadIdx.x;   // B * 256 = 1024
    if (idx >= B_ * HID) return;
    int b = idx >> 8;
    int m = idx & (HID - 1);
    const float* e = g_embd + b * 512;
    const float* w = op_w + (size_t)m * 512;
    float s = op_b[m];
#pragma unroll 8
    for (int c = 0; c < 512; c++) s = fmaf(e[c], w[c], s);
    out[b * HID + m] = s;
}

// ------------------------------------------------------------------------------
extern "C" void kernel_launch(void* const* d_in, const int* in_sizes, int n_in,
                              void* d_out, int out_size)
{
    const float* x      = (const float*)d_in[0];
    const float* ip_w   = (const float*)d_in[1];
    const float* ip_b   = (const float*)d_in[2];
    const float* in_w   = (const float*)d_in[3];
    const float* conv_w = (const float*)d_in[4];
    const float* conv_b = (const float*)d_in[5];
    const float* xproj_w= (const float*)d_in[6];
    const float* dt_w   = (const float*)d_in[7];
    const float* dt_b   = (const float*)d_in[8];
    const float* A_log  = (const float*)d_in[9];
    const float* Dp     = (const float*)d_in[10];
    const float* out_w  = (const float*)d_in[11];
    const float* op_w   = (const float*)d_in[12];
    const float* op_b   = (const float*)d_in[13];
    float* out = (float*)d_out;

    float *ph, *pxz, *pu, *pdbc;
    cudaGetSymbolAddress((void**)&ph,   g_h);
    cudaGetSymbolAddress((void**)&pxz,  g_xz);
    cudaGetSymbolAddress((void**)&pu,   g_u);
    cudaGetSymbolAddress((void**)&pdbc, g_dbc);

    // dynamic smem sizes: 4 stages * (A_T + B_T) floats
    const int smem1 = NSTG * (128 * LDT + 64 * LDT) * (int)sizeof(float);   // NJ=1: 61440
    const int smem2 = NSTG * (128 * LDT + 128 * LDT) * (int)sizeof(float);  // NJ=2: 81920
    cudaFuncSetAttribute(gemm_tc<1, false>, cudaFuncAttributeMaxDynamicSharedMemorySize, smem1);
    cudaFuncSetAttribute(gemm_tc<2, false>, cudaFuncAttributeMaxDynamicSharedMemorySize, smem2);
    cudaFuncSetAttribute(gemm_tc<1, true>,  cudaFuncAttributeMaxDynamicSharedMemorySize, smem1);

    dim3 blk(256);
    // 1) h = x @ ip_w^T + ip_b            [8192,512]x[256,512] -> [8192,256]
    gemm_tc<1, false><<<dim3(HID / 64, BL / 128, 1), blk, smem1>>>(
        x, 0, ip_w, 0, ph, 0, ip_b, BL, HID, 512);
    // 2) xz_dir = h @ in_w[dir]^T          [8192,256]x[1024,256] -> [8192,1024] x2
    gemm_tc<2, false><<<dim3(1024 / 128, BL / 128, 2), blk, smem2>>>(
        ph, 0, in_w, (long)1024 * HID, pxz, (long)BL * 1024, nullptr, BL, 1024, HID);
    // 3) u = silu(depthwise causal conv(xi) + cb), dir-aware time orientation
    conv_silu_kernel<<<(2 * BL * DI) / 256, 256>>>(conv_w, conv_b);
    // 4) dbc = u @ xproj_w[dir]^T          [8192,512]x[48,512] -> [8192,48] x2
    gemm_tc<1, true><<<dim3(1, BL / 128, 2), blk, smem1>>>(
        pu, (long)BL * DI, xproj_w, (long)48 * 512, pdbc, (long)BL * 48, nullptr, BL, 48, 512);
    // 5) chunked scan pass 1 (dt fused; gating + pooling terms fused)
    scan1_kernel<<<2048, 128>>>(A_log, Dp, dt_w, dt_b);
    // 6) chunk combine -> pooled sums (16 lanes per channel, shuffle reduce)
    scan2_kernel<<<256, 256>>>();
    // 7) pooled @ out_w^T (mean folded), concat dirs -> embd
    head1_kernel<<<8, 256>>>(out_w);
    // 8) embd @ op_w^T + op_b -> out
    head2_kernel<<<4, 256>>>(op_w, op_b, out);
}

// round 6
// speedup vs baseline: 1.9699x; 1.3839x over previous
#include <cuda_runtime.h>
#include <cuda_bf16.h>
#include <cstdint>
#include <math.h>
#include <mma.h>

using namespace nvcuda;
typedef __nv_bfloat16 bf16;

static constexpr int B_  = 4;
static constexpr int L_  = 2048;
static constexpr int HID = 256;   // hidden after input proj
static constexpr int DI  = 512;   // d_inner
static constexpr int NS  = 16;    // d_state
static constexpr int RK  = 16;    // dt_rank
static constexpr int NCH = 64;    // chunks
static constexpr int LC  = 32;    // chunk length (NCH*LC == L_)
static constexpr int BL  = B_ * L_;   // 8192

// ---------------- scratch (device globals; no allocations allowed) -------------
__device__ __align__(256) float g_h   [BL * HID];           // input-proj output fp32
__device__ __align__(256) float g_xz  [2 * BL * 2 * DI];    // per-dir xz (xi | z)
__device__ __align__(256) float g_dbc [2 * BL * 48];        // x-proj out (dt_lr|B|C)
__device__ __align__(256) float g_S   [2 * NCH * B_ * DI * NS];
__device__ __align__(256) float g_P   [2 * NCH * B_ * DI * NS];
__device__ __align__(256) float g_Kc  [2 * NCH * B_ * DI * NS];
__device__ __align__(256) float g_al  [2 * NCH * B_ * DI];
__device__ __align__(256) float g_pool[2 * B_ * DI];
__device__ __align__(256) float g_embd[B_ * 2 * HID];
// bf16 hi/lo split operands
__device__ __align__(256) bf16 g_xh  [BL * 512],        g_xl  [BL * 512];
__device__ __align__(256) bf16 g_hh  [BL * HID],        g_hl  [BL * HID];
__device__ __align__(256) bf16 g_uh  [2 * BL * DI],     g_ul  [2 * BL * DI];
__device__ __align__(256) bf16 g_ipwh[HID * 512],       g_ipwl[HID * 512];
__device__ __align__(256) bf16 g_inwh[2 * 1024 * HID],  g_inwl[2 * 1024 * HID];
__device__ __align__(256) bf16 g_xpwh[2 * 48 * 512],    g_xpwl[2 * 48 * 512];

// ---------------- fp32 -> bf16 (hi, lo) split, 4 elems/thread -----------------
__global__ void split_arr(const float* __restrict__ src,
                          bf16* __restrict__ hi, bf16* __restrict__ lo, int n)
{
    int i = (blockIdx.x * blockDim.x + threadIdx.x) * 4;
    if (i >= n) return;
    float4 v = *(const float4*)(src + i);
    float vv[4] = {v.x, v.y, v.z, v.w};
#pragma unroll
    for (int j = 0; j < 4; j++) {
        bf16 h = __float2bfloat16(vv[j]);
        hi[i + j] = h;
        lo[i + j] = __float2bfloat16(vv[j] - __bfloat162float(h));
    }
}

// =================== bf16 tensor-core GEMM (3-term split), cp.async 3-stage ====
// C[M,N] = A[M,K] @ W[N,K]^T (+bias), operands as bf16 (hi, lo) pairs.
// Product al*bh + ah*bl + ah*bh -> ~2^-17 relative error; fp32 accumulate.
// Block tile 128 x (64*NJ) x 16; 256 threads = 8 warps in 2(m) x 4(n).

static constexpr int LDT  = 24;   // bf16 elems per smem row (48B, 16B-aligned)
static constexpr int NSTG = 3;    // pipeline stages

__device__ __forceinline__ void cp16(void* dst, const void* src, int srcbytes) {
    unsigned int d = (unsigned int)__cvta_generic_to_shared(dst);
    asm volatile("cp.async.cg.shared.global [%0], [%1], 16, %2;\n"
                 :: "r"(d), "l"(src), "r"(srcbytes));
}
__device__ __forceinline__ void cp_commit() {
    asm volatile("cp.async.commit_group;\n");
}
template<int Nleft>
__device__ __forceinline__ void cp_wait() {
    asm volatile("cp.async.wait_group %0;\n" :: "n"(Nleft));
}

template<int NJ, bool GUARD>
__global__ void __launch_bounds__(256)
gemm_bf(const bf16* __restrict__ Ah, const bf16* __restrict__ Al, long sA,
        const bf16* __restrict__ Bh, const bf16* __restrict__ Bl, long sB,
        float* __restrict__ C, long sC,
        const float* __restrict__ bias,
        int M, int N, int K)
{
    constexpr int BN  = 64 * NJ;
    constexpr int A_T = 128 * LDT;           // bf16 elems per A tile
    constexpr int B_T = BN * LDT;
    constexpr int STG = 2 * A_T + 2 * B_T;   // hi + lo
    constexpr int LDCs = BN + 4;
    extern __shared__ bf16 smb[];
    float* smf = reinterpret_cast<float*>(smb);   // epilogue/bias alias

    const int t = threadIdx.x;
    const int wid = t >> 5;
    const int wm = wid & 1;        // 0..1  (64-row slab)
    const int wn = wid >> 1;       // 0..3  (16*NJ-col slab)
    const long m0 = (long)blockIdx.y * 128;
    const int  n0 = blockIdx.x * BN;
    Ah += (long)blockIdx.z * sA;  Al += (long)blockIdx.z * sA;
    Bh += (long)blockIdx.z * sB;  Bl += (long)blockIdx.z * sB;
    C  += (long)blockIdx.z * sC;

    // cp.async mapping: 16B = 8 bf16 per chunk; A: thread -> row t>>1, col (t&1)*8
    const int arow = t >> 1;
    const int acol = (t & 1) * 8;
    const bf16* Ahg = Ah + (m0 + arow) * (long)K + acol;
    const bf16* Alg = Al + (m0 + arow) * (long)K + acol;
    // B rows: NJ==2 uses all 256 threads (rows 0..127); NJ==1 threads<128 (rows 0..63)
    const int brow = t >> 1;
    const int bcol = (t & 1) * 8;
    const int bn   = n0 + brow;
    const bool bdo = (NJ == 2) || (t < 128);
    const int  bnc = GUARD ? (bn < N ? bn : 0) : bn;
    const bf16* Bhg = Bh + (long)bnc * K + bcol;
    const bf16* Blg = Bl + (long)bnc * K + bcol;
    const int  bbytes = (!GUARD || bn < N) ? 16 : 0;

    wmma::fragment<wmma::accumulator, 16, 16, 16, float> acc[4][NJ];

    // ---- bias -> accumulator init ----
    if (bias) {
        if (t < BN) {
            float v = (!GUARD || (n0 + t) < N) ? bias[n0 + t] : 0.f;
#pragma unroll
            for (int r = 0; r < 16; r++) smf[r * LDCs + t] = v;
        }
        __syncthreads();
        wmma::fragment<wmma::accumulator, 16, 16, 16, float> bf;
#pragma unroll
        for (int j = 0; j < NJ; j++) {
            wmma::load_matrix_sync(bf, smf + wn * 16 * NJ + j * 16, LDCs, wmma::mem_row_major);
#pragma unroll
            for (int i = 0; i < 4; i++)
#pragma unroll
                for (int e = 0; e < bf.num_elements; e++) acc[i][j].x[e] = bf.x[e];
        }
        __syncthreads();
    } else {
#pragma unroll
        for (int i = 0; i < 4; i++)
#pragma unroll
            for (int j = 0; j < NJ; j++) wmma::fill_fragment(acc[i][j], 0.f);
    }

    // ---- pipeline ----
    auto issue = [&](int s, int k) {
        bf16* st = smb + (size_t)s * STG;
        cp16(st + arow * LDT + acol,       Ahg + k, 16);
        cp16(st + A_T + arow * LDT + acol, Alg + k, 16);
        if (bdo) {
            cp16(st + 2 * A_T + brow * LDT + bcol,       Bhg + k, bbytes);
            cp16(st + 2 * A_T + B_T + brow * LDT + bcol, Blg + k, bbytes);
        }
    };
#pragma unroll
    for (int p = 0; p < NSTG - 1; p++) {
        if (p * 16 < K) issue(p, p * 16);
        cp_commit();
    }

    int s = 0;
    for (int k0 = 0; k0 < K; k0 += 16) {
        cp_wait<NSTG - 2>();
        __syncthreads();

        int kp = k0 + (NSTG - 1) * 16;
        int sp = s + (NSTG - 1); if (sp >= NSTG) sp -= NSTG;
        if (kp < K) issue(sp, kp);
        cp_commit();

        bf16* st = smb + (size_t)s * STG;
        wmma::fragment<wmma::matrix_a, 16, 16, 16, bf16, wmma::row_major> ah[4], al[4];
        wmma::fragment<wmma::matrix_b, 16, 16, 16, bf16, wmma::col_major> bh[NJ], bl[NJ];
#pragma unroll
        for (int i = 0; i < 4; i++) {
            int r = wm * 64 + i * 16;
            wmma::load_matrix_sync(ah[i], st + r * LDT, LDT);
            wmma::load_matrix_sync(al[i], st + A_T + r * LDT, LDT);
        }
#pragma unroll
        for (int j = 0; j < NJ; j++) {
            int c = wn * 16 * NJ + j * 16;
            wmma::load_matrix_sync(bh[j], st + 2 * A_T + c * LDT, LDT);
            wmma::load_matrix_sync(bl[j], st + 2 * A_T + B_T + c * LDT, LDT);
        }
#pragma unroll
        for (int i = 0; i < 4; i++)
#pragma unroll
            for (int j = 0; j < NJ; j++) {
                wmma::mma_sync(acc[i][j], al[i], bh[j], acc[i][j]);
                wmma::mma_sync(acc[i][j], ah[i], bl[j], acc[i][j]);
                wmma::mma_sync(acc[i][j], ah[i], bh[j], acc[i][j]);
            }
        s++; if (s == NSTG) s = 0;
    }

    // ---- epilogue ----
    if (!GUARD) {
#pragma unroll
        for (int i = 0; i < 4; i++)
#pragma unroll
            for (int j = 0; j < NJ; j++)
                wmma::store_matrix_sync(
                    C + (m0 + wm * 64 + i * 16) * (long)N + n0 + wn * 16 * NJ + j * 16,
                    acc[i][j], N, wmma::mem_row_major);
    } else {
        __syncthreads();
        for (int half = 0; half < 2; half++) {
            if (wm == half) {
#pragma unroll
                for (int i = 0; i < 4; i++)
#pragma unroll
                    for (int j = 0; j < NJ; j++)
                        wmma::store_matrix_sync(smf + (i * 16) * LDCs + wn * 16 * NJ + j * 16,
                                                acc[i][j], LDCs, wmma::mem_row_major);
            }
            __syncthreads();
            for (int e = t; e < 64 * BN; e += 256) {
                int r = e / BN, cn = e % BN;
                int n = n0 + cn;
                if (n < N)
                    C[(m0 + half * 64 + r) * (long)N + n] = smf[r * LDCs + cn];
            }
            __syncthreads();
        }
    }
}

// ---------------- depthwise causal conv (dir-aware) + silu -> u hi/lo ---------
__global__ void conv_silu_kernel(const float* __restrict__ cw, const float* __restrict__ cb)
{
    int t = blockIdx.x * blockDim.x + threadIdx.x;   // 2*B*L*DI = 2^23
    int d   = t & (DI - 1);
    int l   = (t >> 9) & (L_ - 1);
    int b   = (t >> 20) & 3;
    int dir = (t >> 22) & 1;
    const float* xi = g_xz + (size_t)dir * BL * 2 * DI;   // xi = first DI cols
    const float* w  = cw + (dir * DI + d) * 4;
    float acc = cb[dir * DI + d];
    if (dir == 0) {
#pragma unroll
        for (int k = 0; k < 4; k++) {
            int ll = l - 3 + k;
            if (ll >= 0) acc = fmaf(w[k], xi[((size_t)b * L_ + ll) * (2 * DI) + d], acc);
        }
    } else {
#pragma unroll
        for (int k = 0; k < 4; k++) {
            int ll = l + 3 - k;
            if (ll < L_) acc = fmaf(w[k], xi[((size_t)b * L_ + ll) * (2 * DI) + d], acc);
        }
    }
    float uvv = acc / (1.f + __expf(-acc));   // silu
    size_t o = (size_t)dir * BL * DI + ((size_t)b * L_ + l) * DI + d;
    bf16 h = __float2bfloat16(uvv);
    g_uh[o] = h;
    g_ul[o] = __float2bfloat16(uvv - __bfloat162float(h));
}

// ---------------- chunked selective scan, pass 1 (dt fused inline) ------------
__global__ void __launch_bounds__(128)
scan1_kernel(const float* __restrict__ A_log, const float* __restrict__ Dp,
             const float* __restrict__ dt_w, const float* __restrict__ dt_b)
{
    int bid = blockIdx.x;                 // 2048 = 2*4*64*4
    int dq  = bid & 3;
    int c   = (bid >> 2) & (NCH - 1);
    int b   = (bid >> 8) & 3;
    int dir = bid >> 10;
    int d   = dq * 128 + threadIdx.x;

    const bf16*  uhp = g_uh  + (size_t)dir * BL * DI;
    const bf16*  ulp = g_ul  + (size_t)dir * BL * DI;
    const float* zp  = g_xz  + (size_t)dir * BL * 2 * DI + DI;   // z half
    const float* dbp = g_dbc + (size_t)dir * BL * 48;

    float a[NS];
#pragma unroll
    for (int n = 0; n < NS; n++) a[n] = -__expf(A_log[(size_t)(dir * DI + d) * NS + n]);
    const float Dv = Dp[dir * DI + d];

    float wreg[RK];
    {
        const float* wr = dt_w + (size_t)(dir * DI + d) * RK;
#pragma unroll
        for (int r = 0; r < RK; r++) wreg[r] = wr[r];
    }
    const float bb = dt_b[dir * DI + d];

    float h[NS], pp[NS], Kk[NS];
#pragma unroll
    for (int n = 0; n < NS; n++) { h[n] = 0.f; pp[n] = 1.f; Kk[n] = 0.f; }
    float accl = 0.f;

    for (int j = 0; j < LC; j++) {
        int s = c * LC + j;
        int l = dir ? (L_ - 1 - s) : s;
        size_t base = (size_t)b * L_ + l;
        float uv = __bfloat162float(uhp[base * DI + d]) + __bfloat162float(ulp[base * DI + d]);
        float zv = zp[base * 2 * DI + d];
        float gate = zv / (1.f + __expf(-zv));

        const float4* rr = (const float4*)(dbp + base * 48);
        float4 p0 = rr[0], p1 = rr[1], p2 = rr[2], p3 = rr[3];   // dt_lr
        float sdt = bb;
        sdt = fmaf(p0.x, wreg[0], sdt);  sdt = fmaf(p0.y, wreg[1], sdt);
        sdt = fmaf(p0.z, wreg[2], sdt);  sdt = fmaf(p0.w, wreg[3], sdt);
        sdt = fmaf(p1.x, wreg[4], sdt);  sdt = fmaf(p1.y, wreg[5], sdt);
        sdt = fmaf(p1.z, wreg[6], sdt);  sdt = fmaf(p1.w, wreg[7], sdt);
        sdt = fmaf(p2.x, wreg[8], sdt);  sdt = fmaf(p2.y, wreg[9], sdt);
        sdt = fmaf(p2.z, wreg[10], sdt); sdt = fmaf(p2.w, wreg[11], sdt);
        sdt = fmaf(p3.x, wreg[12], sdt); sdt = fmaf(p3.y, wreg[13], sdt);
        sdt = fmaf(p3.z, wreg[14], sdt); sdt = fmaf(p3.w, wreg[15], sdt);
        float dtv = (sdt > 15.f) ? sdt : log1pf(__expf(sdt));
        float x = dtv * uv;

        float4 q0 = rr[4], q1 = rr[5], q2 = rr[6], q3 = rr[7];   // B
        float4 q4 = rr[8], q5 = rr[9], q6 = rr[10], q7 = rr[11]; // C
        float Bn[NS] = {q0.x, q0.y, q0.z, q0.w, q1.x, q1.y, q1.z, q1.w,
                        q2.x, q2.y, q2.z, q2.w, q3.x, q3.y, q3.z, q3.w};
        float Cn[NS] = {q4.x, q4.y, q4.z, q4.w, q5.x, q5.y, q5.z, q5.w,
                        q6.x, q6.y, q6.z, q6.w, q7.x, q7.y, q7.z, q7.w};

        float yl = 0.f;
#pragma unroll
        for (int n = 0; n < NS; n++) {
            float dA = __expf(dtv * a[n]);
            h[n]  = fmaf(dA, h[n], x * Bn[n]);
            pp[n] *= dA;
            yl    = fmaf(h[n], Cn[n], yl);
            Kk[n] = fmaf(gate * Cn[n], pp[n], Kk[n]);
        }
        accl = fmaf(gate, fmaf(uv, Dv, yl), accl);
    }

    size_t r = (((size_t)dir * NCH + c) * B_ + b) * DI + d;
    g_al[r] = accl;
#pragma unroll
    for (int n = 0; n < NS; n++) {
        g_S [r * NS + n] = h[n];
        g_P [r * NS + n] = pp[n];
        g_Kc[r * NS + n] = Kk[n];
    }
}

// ---------------- scan combine: 16 lanes per (dir,b,d), shuffle-reduce --------
__global__ void scan2_kernel()
{
    int t = blockIdx.x * blockDim.x + threadIdx.x;   // 65536
    int n   = t & 15;
    int idx = t >> 4;        // 0..4095 = dir*2048 + b*512 + d
    int dir = idx >> 11;
    int b   = (idx >> 9) & 3;
    int d   = idx & (DI - 1);
    float hin = 0.f, acc = 0.f;
    for (int c = 0; c < NCH; c++) {
        size_t r = (((size_t)dir * NCH + c) * B_ + b) * DI + d;
        if (n == 0) acc += g_al[r];
        acc = fmaf(hin, g_Kc[r * NS + n], acc);
        hin = fmaf(g_P[r * NS + n], hin, g_S[r * NS + n]);
    }
#pragma unroll
    for (int o = 8; o; o >>= 1) acc += __shfl_down_sync(0xffffffffu, acc, o, 16);
    if (n == 0) g_pool[idx] = acc;
}

// ---------------- head: pooled @ out_w^T (per dir) -> embd --------------------
__global__ void head1_kernel(const float* __restrict__ out_w)
{
    int idx = blockIdx.x * blockDim.x + threadIdx.x;   // B * 512 = 2048
    if (idx >= B_ * 2 * HID) return;
    int b = idx >> 9;
    int cf = idx & 511;
    int dir = cf >> 8;
    int cc = cf & (HID - 1);
    const float* pr = g_pool + dir * B_ * DI + b * DI;
    const float* wr = out_w + ((size_t)dir * HID + cc) * DI;
    float s = 0.f;
#pragma unroll 8
    for (int k = 0; k < DI; k++) s = fmaf(pr[k], wr[k], s);
    g_embd[b * 512 + cf] = s * (1.f / (float)L_);
}

// ---------------- head: embd @ op_w^T + op_b ----------------------------------
__global__ void head2_kernel(const float* __restrict__ op_w, const float* __restrict__ op_b,
                             float* __restrict__ out)
{
    int idx = blockIdx.x * blockDim.x + threadIdx.x;   // B * 256 = 1024
    if (idx >= B_ * HID) return;
    int b = idx >> 8;
    int m = idx & (HID - 1);
    const float* e = g_embd + b * 512;
    const float* w = op_w + (size_t)m * 512;
    float s = op_b[m];
#pragma unroll 8
    for (int c = 0; c < 512; c++) s = fmaf(e[c], w[c], s);
    out[b * HID + m] = s;
}

// ------------------------------------------------------------------------------
extern "C" void kernel_launch(void* const* d_in, const int* in_sizes, int n_in,
                              void* d_out, int out_size)
{
    const float* x      = (const float*)d_in[0];
    const float* ip_w   = (const float*)d_in[1];
    const float* ip_b   = (const float*)d_in[2];
    const float* in_w   = (const float*)d_in[3];
    const float* conv_w = (const float*)d_in[4];
    const float* conv_b = (const float*)d_in[5];
    const float* xproj_w= (const float*)d_in[6];
    const float* dt_w   = (const float*)d_in[7];
    const float* dt_b   = (const float*)d_in[8];
    const float* A_log  = (const float*)d_in[9];
    const float* Dp     = (const float*)d_in[10];
    const float* out_w  = (const float*)d_in[11];
    const float* op_w   = (const float*)d_in[12];
    const float* op_b   = (const float*)d_in[13];
    float* out = (float*)d_out;

    float *ph, *pxz, *pdbc;
    bf16 *pxh, *pxl, *phh, *phl, *puh, *pul, *pipwh, *pipwl, *pinwh, *pinwl, *pxpwh, *pxpwl;
    cudaGetSymbolAddress((void**)&ph,    g_h);
    cudaGetSymbolAddress((void**)&pxz,   g_xz);
    cudaGetSymbolAddress((void**)&pdbc,  g_dbc);
    cudaGetSymbolAddress((void**)&pxh,   g_xh);
    cudaGetSymbolAddress((void**)&pxl,   g_xl);
    cudaGetSymbolAddress((void**)&phh,   g_hh);
    cudaGetSymbolAddress((void**)&phl,   g_hl);
    cudaGetSymbolAddress((void**)&puh,   g_uh);
    cudaGetSymbolAddress((void**)&pul,   g_ul);
    cudaGetSymbolAddress((void**)&pipwh, g_ipwh);
    cudaGetSymbolAddress((void**)&pipwl, g_ipwl);
    cudaGetSymbolAddress((void**)&pinwh, g_inwh);
    cudaGetSymbolAddress((void**)&pinwl, g_inwl);
    cudaGetSymbolAddress((void**)&pxpwh, g_xpwh);
    cudaGetSymbolAddress((void**)&pxpwl, g_xpwl);

    // dynamic smem: 3 stages * (2*A_T + 2*B_T) bf16
    const int smem1 = NSTG * (2 * 128 * LDT + 2 * 64 * LDT) * (int)sizeof(bf16);   // 55296
    const int smem2 = NSTG * (2 * 128 * LDT + 2 * 128 * LDT) * (int)sizeof(bf16);  // 73728
    cudaFuncSetAttribute(gemm_bf<1, false>, cudaFuncAttributeMaxDynamicSharedMemorySize, smem1);
    cudaFuncSetAttribute(gemm_bf<2, false>, cudaFuncAttributeMaxDynamicSharedMemorySize, smem2);
    cudaFuncSetAttribute(gemm_bf<1, true>,  cudaFuncAttributeMaxDynamicSharedMemorySize, smem1);

    dim3 blk(256);
    // 0) split x and weights into bf16 (hi, lo)
    split_arr<<<(BL * 512 / 4 + 255) / 256, 256>>>(x, pxh, pxl, BL * 512);
    split_arr<<<(HID * 512 / 4 + 255) / 256, 256>>>(ip_w, pipwh, pipwl, HID * 512);
    split_arr<<<(2 * 1024 * HID / 4 + 255) / 256, 256>>>(in_w, pinwh, pinwl, 2 * 1024 * HID);
    split_arr<<<(2 * 48 * 512 / 4 + 255) / 256, 256>>>(xproj_w, pxpwh, pxpwl, 2 * 48 * 512);

    // 1) h = x @ ip_w^T + ip_b            [8192,512]x[256,512] -> [8192,256]
    gemm_bf<1, false><<<dim3(HID / 64, BL / 128, 1), blk, smem1>>>(
        pxh, pxl, 0, pipwh, pipwl, 0, ph, 0, ip_b, BL, HID, 512);
    split_arr<<<(BL * HID / 4 + 255) / 256, 256>>>(ph, phh, phl, BL * HID);

    // 2) xz_dir = h @ in_w[dir]^T          [8192,256]x[1024,256] -> [8192,1024] x2
    gemm_bf<2, false><<<dim3(1024 / 128, BL / 128, 2), blk, smem2>>>(
        phh, phl, 0, pinwh, pinwl, (long)1024 * HID, pxz, (long)BL * 1024, nullptr,
        BL, 1024, HID);

    // 3) u = silu(depthwise causal conv(xi) + cb) -> bf16 hi/lo
    conv_silu_kernel<<<(2 * BL * DI) / 256, 256>>>(conv_w, conv_b);

    // 4) dbc = u @ xproj_w[dir]^T          [8192,512]x[48,512] -> [8192,48] x2
    gemm_bf<1, true><<<dim3(1, BL / 128, 2), blk, smem1>>>(
        puh, pul, (long)BL * DI, pxpwh, pxpwl, (long)48 * 512, pdbc, (long)BL * 48, nullptr,
        BL, 48, 512);

    // 5) chunked scan pass 1 (dt fused; gating + pooling terms fused)
    scan1_kernel<<<2048, 128>>>(A_log, Dp, dt_w, dt_b);
    // 6) chunk combine -> pooled sums
    scan2_kernel<<<256, 256>>>();
    // 7) pooled @ out_w^T (mean folded), concat dirs -> embd
    head1_kernel<<<8, 256>>>(out_w);
    // 8) embd @ op_w^T + op_b -> out
    head2_kernel<<<4, 256>>>(op_w, op_b, out);
}

// round 7
// speedup vs baseline: 2.1052x; 1.0687x over previous
#include <cuda_runtime.h>
#include <cuda_bf16.h>
#include <cstdint>
#include <math.h>
#include <mma.h>

using namespace nvcuda;
typedef __nv_bfloat16 bf16;

static constexpr int B_  = 4;
static constexpr int L_  = 2048;
static constexpr int HID = 256;   // hidden after input proj
static constexpr int DI  = 512;   // d_inner
static constexpr int NS  = 16;    // d_state
static constexpr int RK  = 16;    // dt_rank
static constexpr int NCH = 64;    // chunks
static constexpr int LC  = 32;    // chunk length (NCH*LC == L_)
static constexpr int BL  = B_ * L_;   // 8192

// ---------------- scratch (device globals; no allocations allowed) -------------
__device__ __align__(256) float g_xz  [2 * BL * 2 * DI];    // per-dir xz (xi | z)
__device__ __align__(256) float g_dbc [2 * BL * 48];        // x-proj out (dt_lr|B|C)
__device__ __align__(256) float g_S   [2 * NCH * B_ * DI * NS];
__device__ __align__(256) float g_P   [2 * NCH * B_ * DI * NS];
__device__ __align__(256) float g_Kc  [2 * NCH * B_ * DI * NS];
__device__ __align__(256) float g_al  [2 * NCH * B_ * DI];
__device__ __align__(256) float g_pool[2 * B_ * DI];
__device__ __align__(256) float g_embd[B_ * 2 * HID];
// bf16 hi/lo split operands
__device__ __align__(256) bf16 g_xh  [BL * 512],        g_xl  [BL * 512];
__device__ __align__(256) bf16 g_hh  [BL * HID],        g_hl  [BL * HID];
__device__ __align__(256) bf16 g_uh  [2 * BL * DI],     g_ul  [2 * BL * DI];
__device__ __align__(256) bf16 g_ipwh[HID * 512],       g_ipwl[HID * 512];
__device__ __align__(256) bf16 g_inwh[2 * 1024 * HID],  g_inwl[2 * 1024 * HID];
__device__ __align__(256) bf16 g_xpwh[2 * 48 * 512],    g_xpwl[2 * 48 * 512];

// ---------------- fp32 -> bf16 (hi, lo) splits --------------------------------
__global__ void split_x(const float* __restrict__ src,
                        bf16* __restrict__ hi, bf16* __restrict__ lo, int n)
{
    int i = (blockIdx.x * blockDim.x + threadIdx.x) * 4;
    if (i >= n) return;
    float4 v = *(const float4*)(src + i);
    float vv[4] = {v.x, v.y, v.z, v.w};
#pragma unroll
    for (int j = 0; j < 4; j++) {
        bf16 h = __float2bfloat16(vv[j]);
        hi[i + j] = h;
        lo[i + j] = __float2bfloat16(vv[j] - __bfloat162float(h));
    }
}

// all three weight splits in one launch
__global__ void split_w(const float* __restrict__ w1, bf16* __restrict__ h1, bf16* __restrict__ l1, int n1,
                        const float* __restrict__ w2, bf16* __restrict__ h2, bf16* __restrict__ l2, int n2,
                        const float* __restrict__ w3, bf16* __restrict__ h3, bf16* __restrict__ l3, int n3)
{
    int i = (blockIdx.x * blockDim.x + threadIdx.x) * 4;
    const float* s; bf16 *ph, *pl; int off;
    if (i < n1)                { s = w1; ph = h1; pl = l1; off = i; }
    else if (i < n1 + n2)      { s = w2; ph = h2; pl = l2; off = i - n1; }
    else if (i < n1 + n2 + n3) { s = w3; ph = h3; pl = l3; off = i - n1 - n2; }
    else return;
    float4 v = *(const float4*)(s + off);
    float vv[4] = {v.x, v.y, v.z, v.w};
#pragma unroll
    for (int j = 0; j < 4; j++) {
        bf16 h = __float2bfloat16(vv[j]);
        ph[off + j] = h;
        pl[off + j] = __float2bfloat16(vv[j] - __bfloat162float(h));
    }
}

// =================== bf16 tensor-core GEMM (3-term split), cp.async 3-stage ====
// C[M,N] = A[M,K] @ W[N,K]^T (+bias), operands as bf16 (hi, lo) pairs.
// Product al*bh + ah*bl + ah*bh -> ~2^-17 relative error; fp32 accumulate.
// Block tile 128 x (64*NJ) x 16; 256 threads = 8 warps in 2(m) x 4(n).
// OUTSPLIT: epilogue emits bf16 (hi, lo) instead of fp32 C.

static constexpr int LDT  = 24;   // bf16 elems per smem row (48B, 16B-aligned)
static constexpr int NSTG = 3;    // pipeline stages

__device__ __forceinline__ void cp16(void* dst, const void* src, int srcbytes) {
    unsigned int d = (unsigned int)__cvta_generic_to_shared(dst);
    asm volatile("cp.async.cg.shared.global [%0], [%1], 16, %2;\n"
                 :: "r"(d), "l"(src), "r"(srcbytes));
}
__device__ __forceinline__ void cp_commit() {
    asm volatile("cp.async.commit_group;\n");
}
template<int Nleft>
__device__ __forceinline__ void cp_wait() {
    asm volatile("cp.async.wait_group %0;\n" :: "n"(Nleft));
}

template<int NJ, bool GUARD, bool OUTSPLIT>
__global__ void __launch_bounds__(256)
gemm_bf(const bf16* __restrict__ Ah, const bf16* __restrict__ Al, long sA,
        const bf16* __restrict__ Bh, const bf16* __restrict__ Bl, long sB,
        float* __restrict__ C, bf16* __restrict__ Chi, bf16* __restrict__ Clo, long sC,
        const float* __restrict__ bias,
        int M, int N, int K)
{
    constexpr int BN  = 64 * NJ;
    constexpr int A_T = 128 * LDT;           // bf16 elems per A tile
    constexpr int B_T = BN * LDT;
    constexpr int STG = 2 * A_T + 2 * B_T;   // hi + lo
    constexpr int LDCs = BN + 4;
    extern __shared__ bf16 smb[];
    float* smf = reinterpret_cast<float*>(smb);   // epilogue/bias alias

    const int t = threadIdx.x;
    const int wid = t >> 5;
    const int wm = wid & 1;        // 0..1  (64-row slab)
    const int wn = wid >> 1;       // 0..3  (16*NJ-col slab)
    const long m0 = (long)blockIdx.y * 128;
    const int  n0 = blockIdx.x * BN;
    Ah += (long)blockIdx.z * sA;  Al += (long)blockIdx.z * sA;
    Bh += (long)blockIdx.z * sB;  Bl += (long)blockIdx.z * sB;
    if (C)   C   += (long)blockIdx.z * sC;
    if (Chi) { Chi += (long)blockIdx.z * sC; Clo += (long)blockIdx.z * sC; }

    const int arow = t >> 1;
    const int acol = (t & 1) * 8;
    const bf16* Ahg = Ah + (m0 + arow) * (long)K + acol;
    const bf16* Alg = Al + (m0 + arow) * (long)K + acol;
    const int brow = t >> 1;
    const int bcol = (t & 1) * 8;
    const int bn   = n0 + brow;
    const bool bdo = (NJ == 2) || (t < 128);
    const int  bnc = GUARD ? (bn < N ? bn : 0) : bn;
    const bf16* Bhg = Bh + (long)bnc * K + bcol;
    const bf16* Blg = Bl + (long)bnc * K + bcol;
    const int  bbytes = (!GUARD || bn < N) ? 16 : 0;

    wmma::fragment<wmma::accumulator, 16, 16, 16, float> acc[4][NJ];

    // ---- bias -> accumulator init ----
    if (bias) {
        if (t < BN) {
            float v = (!GUARD || (n0 + t) < N) ? bias[n0 + t] : 0.f;
#pragma unroll
            for (int r = 0; r < 16; r++) smf[r * LDCs + t] = v;
        }
        __syncthreads();
        wmma::fragment<wmma::accumulator, 16, 16, 16, float> bf;
#pragma unroll
        for (int j = 0; j < NJ; j++) {
            wmma::load_matrix_sync(bf, smf + wn * 16 * NJ + j * 16, LDCs, wmma::mem_row_major);
#pragma unroll
            for (int i = 0; i < 4; i++)
#pragma unroll
                for (int e = 0; e < bf.num_elements; e++) acc[i][j].x[e] = bf.x[e];
        }
        __syncthreads();
    } else {
#pragma unroll
        for (int i = 0; i < 4; i++)
#pragma unroll
            for (int j = 0; j < NJ; j++) wmma::fill_fragment(acc[i][j], 0.f);
    }

    // ---- pipeline ----
    auto issue = [&](int s, int k) {
        bf16* st = smb + (size_t)s * STG;
        cp16(st + arow * LDT + acol,       Ahg + k, 16);
        cp16(st + A_T + arow * LDT + acol, Alg + k, 16);
        if (bdo) {
            cp16(st + 2 * A_T + brow * LDT + bcol,       Bhg + k, bbytes);
            cp16(st + 2 * A_T + B_T + brow * LDT + bcol, Blg + k, bbytes);
        }
    };
#pragma unroll
    for (int p = 0; p < NSTG - 1; p++) {
        if (p * 16 < K) issue(p, p * 16);
        cp_commit();
    }

    int s = 0;
    for (int k0 = 0; k0 < K; k0 += 16) {
        cp_wait<NSTG - 2>();
        __syncthreads();

        int kp = k0 + (NSTG - 1) * 16;
        int sp = s + (NSTG - 1); if (sp >= NSTG) sp -= NSTG;
        if (kp < K) issue(sp, kp);
        cp_commit();

        bf16* st = smb + (size_t)s * STG;
        wmma::fragment<wmma::matrix_a, 16, 16, 16, bf16, wmma::row_major> ah[4], al[4];
        wmma::fragment<wmma::matrix_b, 16, 16, 16, bf16, wmma::col_major> bh[NJ], bl[NJ];
#pragma unroll
        for (int i = 0; i < 4; i++) {
            int r = wm * 64 + i * 16;
            wmma::load_matrix_sync(ah[i], st + r * LDT, LDT);
            wmma::load_matrix_sync(al[i], st + A_T + r * LDT, LDT);
        }
#pragma unroll
        for (int j = 0; j < NJ; j++) {
            int c = wn * 16 * NJ + j * 16;
            wmma::load_matrix_sync(bh[j], st + 2 * A_T + c * LDT, LDT);
            wmma::load_matrix_sync(bl[j], st + 2 * A_T + B_T + c * LDT, LDT);
        }
#pragma unroll
        for (int i = 0; i < 4; i++)
#pragma unroll
            for (int j = 0; j < NJ; j++) {
                wmma::mma_sync(acc[i][j], al[i], bh[j], acc[i][j]);
                wmma::mma_sync(acc[i][j], ah[i], bl[j], acc[i][j]);
                wmma::mma_sync(acc[i][j], ah[i], bh[j], acc[i][j]);
            }
        s++; if (s == NSTG) s = 0;
    }

    // ---- epilogue ----
    if (OUTSPLIT) {
        // stage to smem (128 x LDCs fp32), then emit bf16 hi/lo
        __syncthreads();
#pragma unroll
        for (int i = 0; i < 4; i++)
#pragma unroll
            for (int j = 0; j < NJ; j++)
                wmma::store_matrix_sync(smf + (wm * 64 + i * 16) * LDCs + wn * 16 * NJ + j * 16,
                                        acc[i][j], LDCs, wmma::mem_row_major);
        __syncthreads();
        for (int e = t; e < 128 * BN; e += 256) {
            int r = e / BN, cn = e % BN;
            float v = smf[r * LDCs + cn];
            bf16 h = __float2bfloat16(v);
            long o = (m0 + r) * (long)N + n0 + cn;
            Chi[o] = h;
            Clo[o] = __float2bfloat16(v - __bfloat162float(h));
        }
    } else if (!GUARD) {
#pragma unroll
        for (int i = 0; i < 4; i++)
#pragma unroll
            for (int j = 0; j < NJ; j++)
                wmma::store_matrix_sync(
                    C + (m0 + wm * 64 + i * 16) * (long)N + n0 + wn * 16 * NJ + j * 16,
                    acc[i][j], N, wmma::mem_row_major);
    } else {
        __syncthreads();
        for (int half = 0; half < 2; half++) {
            if (wm == half) {
#pragma unroll
                for (int i = 0; i < 4; i++)
#pragma unroll
                    for (int j = 0; j < NJ; j++)
                        wmma::store_matrix_sync(smf + (i * 16) * LDCs + wn * 16 * NJ + j * 16,
                                                acc[i][j], LDCs, wmma::mem_row_major);
            }
            __syncthreads();
            for (int e = t; e < 64 * BN; e += 256) {
                int r = e / BN, cn = e % BN;
                int n = n0 + cn;
                if (n < N)
                    C[(m0 + half * 64 + r) * (long)N + n] = smf[r * LDCs + cn];
            }
            __syncthreads();
        }
    }
}

// ---------------- depthwise causal conv (dir-aware) + silu -> u hi/lo ---------
__global__ void conv_silu_kernel(const float* __restrict__ cw, const float* __restrict__ cb)
{
    int t = blockIdx.x * blockDim.x + threadIdx.x;   // 2*B*L*DI = 2^23
    int d   = t & (DI - 1);
    int l   = (t >> 9) & (L_ - 1);
    int b   = (t >> 20) & 3;
    int dir = (t >> 22) & 1;
    const float* xi = g_xz + (size_t)dir * BL * 2 * DI;   // xi = first DI cols
    const float* w  = cw + (dir * DI + d) * 4;
    float acc = cb[dir * DI + d];
    if (dir == 0) {
#pragma unroll
        for (int k = 0; k < 4; k++) {
            int ll = l - 3 + k;
            if (ll >= 0) acc = fmaf(w[k], xi[((size_t)b * L_ + ll) * (2 * DI) + d], acc);
        }
    } else {
#pragma unroll
        for (int k = 0; k < 4; k++) {
            int ll = l + 3 - k;
            if (ll < L_) acc = fmaf(w[k], xi[((size_t)b * L_ + ll) * (2 * DI) + d], acc);
        }
    }
    float uvv = acc / (1.f + __expf(-acc));   // silu
    size_t o = (size_t)dir * BL * DI + ((size_t)b * L_ + l) * DI + d;
    bf16 h = __float2bfloat16(uvv);
    g_uh[o] = h;
    g_ul[o] = __float2bfloat16(uvv - __bfloat162float(h));
}

// ---------------- chunked selective scan, pass 1 (dt fused inline) ------------
__global__ void __launch_bounds__(128)
scan1_kernel(const float* __restrict__ A_log, const float* __restrict__ Dp,
             const float* __restrict__ dt_w, const float* __restrict__ dt_b)
{
    int bid = blockIdx.x;                 // 2048 = 2*4*64*4
    int dq  = bid & 3;
    int c   = (bid >> 2) & (NCH - 1);
    int b   = (bid >> 8) & 3;
    int dir = bid >> 10;
    int d   = dq * 128 + threadIdx.x;

    const bf16*  uhp = g_uh  + (size_t)dir * BL * DI;
    const bf16*  ulp = g_ul  + (size_t)dir * BL * DI;
    const float* zp  = g_xz  + (size_t)dir * BL * 2 * DI + DI;   // z half
    const float* dbp = g_dbc + (size_t)dir * BL * 48;

    float a[NS];
#pragma unroll
    for (int n = 0; n < NS; n++) a[n] = -__expf(A_log[(size_t)(dir * DI + d) * NS + n]);
    const float Dv = Dp[dir * DI + d];

    float wreg[RK];
    {
        const float* wr = dt_w + (size_t)(dir * DI + d) * RK;
#pragma unroll
        for (int r = 0; r < RK; r++) wreg[r] = wr[r];
    }
    const float bb = dt_b[dir * DI + d];

    float h[NS], pp[NS], Kk[NS];
#pragma unroll
    for (int n = 0; n < NS; n++) { h[n] = 0.f; pp[n] = 1.f; Kk[n] = 0.f; }
    float accl = 0.f;

    for (int j = 0; j < LC; j++) {
        int s = c * LC + j;
        int l = dir ? (L_ - 1 - s) : s;
        size_t base = (size_t)b * L_ + l;
        float uv = __bfloat162float(uhp[base * DI + d]) + __bfloat162float(ulp[base * DI + d]);
        float zv = zp[base * 2 * DI + d];
        float gate = zv / (1.f + __expf(-zv));

        const float4* rr = (const float4*)(dbp + base * 48);
        float4 p0 = rr[0], p1 = rr[1], p2 = rr[2], p3 = rr[3];   // dt_lr
        float sdt = bb;
        sdt = fmaf(p0.x, wreg[0], sdt);  sdt = fmaf(p0.y, wreg[1], sdt);
        sdt = fmaf(p0.z, wreg[2], sdt);  sdt = fmaf(p0.w, wreg[3], sdt);
        sdt = fmaf(p1.x, wreg[4], sdt);  sdt = fmaf(p1.y, wreg[5], sdt);
        sdt = fmaf(p1.z, wreg[6], sdt);  sdt = fmaf(p1.w, wreg[7], sdt);
        sdt = fmaf(p2.x, wreg[8], sdt);  sdt = fmaf(p2.y, wreg[9], sdt);
        sdt = fmaf(p2.z, wreg[10], sdt); sdt = fmaf(p2.w, wreg[11], sdt);
        sdt = fmaf(p3.x, wreg[12], sdt); sdt = fmaf(p3.y, wreg[13], sdt);
        sdt = fmaf(p3.z, wreg[14], sdt); sdt = fmaf(p3.w, wreg[15], sdt);
        float dtv = (sdt > 15.f) ? sdt : log1pf(__expf(sdt));
        float x = dtv * uv;

        float4 q0 = rr[4], q1 = rr[5], q2 = rr[6], q3 = rr[7];   // B
        float4 q4 = rr[8], q5 = rr[9], q6 = rr[10], q7 = rr[11]; // C
        float Bn[NS] = {q0.x, q0.y, q0.z, q0.w, q1.x, q1.y, q1.z, q1.w,
                        q2.x, q2.y, q2.z, q2.w, q3.x, q3.y, q3.z, q3.w};
        float Cn[NS] = {q4.x, q4.y, q4.z, q4.w, q5.x, q5.y, q5.z, q5.w,
                        q6.x, q6.y, q6.z, q6.w, q7.x, q7.y, q7.z, q7.w};

        float yl = 0.f;
#pragma unroll
        for (int n = 0; n < NS; n++) {
            float dA = __expf(dtv * a[n]);
            h[n]  = fmaf(dA, h[n], x * Bn[n]);
            pp[n] *= dA;
            yl    = fmaf(h[n], Cn[n], yl);
            Kk[n] = fmaf(gate * Cn[n], pp[n], Kk[n]);
        }
        accl = fmaf(gate, fmaf(uv, Dv, yl), accl);
    }

    size_t r = (((size_t)dir * NCH + c) * B_ + b) * DI + d;
    g_al[r] = accl;
#pragma unroll
    for (int n = 0; n < NS; n++) {
        g_S [r * NS + n] = h[n];
        g_P [r * NS + n] = pp[n];
        g_Kc[r * NS + n] = Kk[n];
    }
}

// ---------------- scan combine: 16 lanes per (dir,b,d), shuffle-reduce --------
__global__ void scan2_kernel()
{
    int t = blockIdx.x * blockDim.x + threadIdx.x;   // 65536
    int n   = t & 15;
    int idx = t >> 4;        // 0..4095 = dir*2048 + b*512 + d
    int dir = idx >> 11;
    int b   = (idx >> 9) & 3;
    int d   = idx & (DI - 1);
    float hin = 0.f, acc = 0.f;
    for (int c = 0; c < NCH; c++) {
        size_t r = (((size_t)dir * NCH + c) * B_ + b) * DI + d;
        if (n == 0) acc += g_al[r];
        acc = fmaf(hin, g_Kc[r * NS + n], acc);
        hin = fmaf(g_P[r * NS + n], hin, g_S[r * NS + n]);
    }
#pragma unroll
    for (int o = 8; o; o >>= 1) acc += __shfl_down_sync(0xffffffffu, acc, o, 16);
    if (n == 0) g_pool[idx] = acc;
}

// ---------------- head: pooled @ out_w^T (per dir) -> embd --------------------
__global__ void head1_kernel(const float* __restrict__ out_w)
{
    int idx = blockIdx.x * blockDim.x + threadIdx.x;   // B * 512 = 2048
    if (idx >= B_ * 2 * HID) return;
    int b = idx >> 9;
    int cf = idx & 511;
    int dir = cf >> 8;
    int cc = cf & (HID - 1);
    const float* pr = g_pool + dir * B_ * DI + b * DI;
    const float* wr = out_w + ((size_t)dir * HID + cc) * DI;
    float s = 0.f;
#pragma unroll 8
    for (int k = 0; k < DI; k++) s = fmaf(pr[k], wr[k], s);
    g_embd[b * 512 + cf] = s * (1.f / (float)L_);
}

// ---------------- head: embd @ op_w^T + op_b ----------------------------------
__global__ void head2_kernel(const float* __restrict__ op_w, const float* __restrict__ op_b,
                             float* __restrict__ out)
{
    int idx = blockIdx.x * blockDim.x + threadIdx.x;   // B * 256 = 1024
    if (idx >= B_ * HID) return;
    int b = idx >> 8;
    int m = idx & (HID - 1);
    const float* e = g_embd + b * 512;
    const float* w = op_w + (size_t)m * 512;
    float s = op_b[m];
#pragma unroll 8
    for (int c = 0; c < 512; c++) s = fmaf(e[c], w[c], s);
    out[b * HID + m] = s;
}

// ------------------------------------------------------------------------------
extern "C" void kernel_launch(void* const* d_in, const int* in_sizes, int n_in,
                              void* d_out, int out_size)
{
    const float* x      = (const float*)d_in[0];
    const float* ip_w   = (const float*)d_in[1];
    const float* ip_b   = (const float*)d_in[2];
    const float* in_w   = (const float*)d_in[3];
    const float* conv_w = (const float*)d_in[4];
    const float* conv_b = (const float*)d_in[5];
    const float* xproj_w= (const float*)d_in[6];
    const float* dt_w   = (const float*)d_in[7];
    const float* dt_b   = (const float*)d_in[8];
    const float* A_log  = (const float*)d_in[9];
    const float* Dp     = (const float*)d_in[10];
    const float* out_w  = (const float*)d_in[11];
    const float* op_w   = (const float*)d_in[12];
    const float* op_b   = (const float*)d_in[13];
    float* out = (float*)d_out;

    float *pxz, *pdbc;
    bf16 *pxh, *pxl, *phh, *phl, *puh, *pul, *pipwh, *pipwl, *pinwh, *pinwl, *pxpwh, *pxpwl;
    cudaGetSymbolAddress((void**)&pxz,   g_xz);
    cudaGetSymbolAddress((void**)&pdbc,  g_dbc);
    cudaGetSymbolAddress((void**)&pxh,   g_xh);
    cudaGetSymbolAddress((void**)&pxl,   g_xl);
    cudaGetSymbolAddress((void**)&phh,   g_hh);
    cudaGetSymbolAddress((void**)&phl,   g_hl);
    cudaGetSymbolAddress((void**)&puh,   g_uh);
    cudaGetSymbolAddress((void**)&pul,   g_ul);
    cudaGetSymbolAddress((void**)&pipwh, g_ipwh);
    cudaGetSymbolAddress((void**)&pipwl, g_ipwl);
    cudaGetSymbolAddress((void**)&pinwh, g_inwh);
    cudaGetSymbolAddress((void**)&pinwl, g_inwl);
    cudaGetSymbolAddress((void**)&pxpwh, g_xpwh);
    cudaGetSymbolAddress((void**)&pxpwl, g_xpwl);

    const int smem1 = NSTG * (2 * 128 * LDT + 2 * 64 * LDT) * (int)sizeof(bf16);   // 55296
    const int smem2 = NSTG * (2 * 128 * LDT + 2 * 128 * LDT) * (int)sizeof(bf16);  // 73728
    cudaFuncSetAttribute(gemm_bf<1, false, true>,  cudaFuncAttributeMaxDynamicSharedMemorySize, smem1);
    cudaFuncSetAttribute(gemm_bf<2, false, false>, cudaFuncAttributeMaxDynamicSharedMemorySize, smem2);
    cudaFuncSetAttribute(gemm_bf<1, true, false>,  cudaFuncAttributeMaxDynamicSharedMemorySize, smem1);

    dim3 blk(256);
    const int n1 = HID * 512, n2 = 2 * 1024 * HID, n3 = 2 * 48 * 512;

    // 1) split x -> bf16 hi/lo
    split_x<<<(BL * 512 / 4 + 255) / 256, 256>>>(x, pxh, pxl, BL * 512);
    // 2) split all weights (one launch)
    split_w<<<((n1 + n2 + n3) / 4 + 255) / 256, 256>>>(
        ip_w, pipwh, pipwl, n1, in_w, pinwh, pinwl, n2, xproj_w, pxpwh, pxpwl, n3);
    // 3) h = x @ ip_w^T + ip_b -> bf16 hi/lo directly   [8192,512]x[256,512]
    gemm_bf<1, false, true><<<dim3(HID / 64, BL / 128, 1), blk, smem1>>>(
        pxh, pxl, 0, pipwh, pipwl, 0, nullptr, phh, phl, 0, ip_b, BL, HID, 512);
    // 4) xz_dir = h @ in_w[dir]^T   [8192,256]x[1024,256] -> [8192,1024] x2  (PROFILED)
    gemm_bf<2, false, false><<<dim3(1024 / 128, BL / 128, 2), blk, smem2>>>(
        phh, phl, 0, pinwh, pinwl, (long)1024 * HID, pxz, nullptr, nullptr, (long)BL * 1024,
        nullptr, BL, 1024, HID);
    // 5) u = silu(depthwise causal conv(xi) + cb) -> bf16 hi/lo
    conv_silu_kernel<<<(2 * BL * DI) / 256, 256>>>(conv_w, conv_b);
    // 6) dbc = u @ xproj_w[dir]^T   [8192,512]x[48,512] -> [8192,48] x2
    gemm_bf<1, true, false><<<dim3(1, BL / 128, 2), blk, smem1>>>(
        puh, pul, (long)BL * DI, pxpwh, pxpwl, (long)48 * 512, pdbc, nullptr, nullptr,
        (long)BL * 48, nullptr, BL, 48, 512);
    // 7) chunked scan pass 1 (dt fused; gating + pooling terms fused)
    scan1_kernel<<<2048, 128>>>(A_log, Dp, dt_w, dt_b);
    // 8) chunk combine -> pooled sums
    scan2_kernel<<<256, 256>>>();
    // 9) pooled @ out_w^T (mean folded), concat dirs -> embd
    head1_kernel<<<8, 256>>>(out_w);
    // 10) embd @ op_w^T + op_b -> out
    head2_kernel<<<4, 256>>>(op_w, op_b, out);
}

// round 8
// speedup vs baseline: 2.1494x; 1.0210x over previous
#include <cuda_runtime.h>
#include <cuda_bf16.h>
#include <cstdint>
#include <math.h>
#include <mma.h>

using namespace nvcuda;
typedef __nv_bfloat16 bf16;

static constexpr int B_  = 4;
static constexpr int L_  = 2048;
static constexpr int HID = 256;   // hidden after input proj
static constexpr int DI  = 512;   // d_inner
static constexpr int NS  = 16;    // d_state
static constexpr int RK  = 16;    // dt_rank
static constexpr int NCH = 64;    // chunks
static constexpr int LC  = 32;    // chunk length (NCH*LC == L_)
static constexpr int BL  = B_ * L_;   // 8192

// ---------------- scratch (device globals; no allocations allowed) -------------
__device__ __align__(256) float g_xz  [2 * BL * 2 * DI];    // per-dir xz (xi | z)
__device__ __align__(256) float g_dbc [2 * BL * 48];        // x-proj out (dt_lr|B|C)
__device__ __align__(256) float g_S   [2 * NCH * B_ * DI * NS];
__device__ __align__(256) float g_P   [2 * NCH * B_ * DI * NS];
__device__ __align__(256) float g_Kc  [2 * NCH * B_ * DI * NS];
__device__ __align__(256) float g_al  [2 * NCH * B_ * DI];
__device__ __align__(256) float g_pool[2 * B_ * DI];
__device__ __align__(256) float g_embd[B_ * 2 * HID];
// bf16 hi/lo split operands
__device__ __align__(256) bf16 g_xh  [BL * 512],        g_xl  [BL * 512];
__device__ __align__(256) bf16 g_hh  [BL * HID],        g_hl  [BL * HID];
__device__ __align__(256) bf16 g_uh  [2 * BL * DI],     g_ul  [2 * BL * DI];
__device__ __align__(256) bf16 g_ipwh[HID * 512],       g_ipwl[HID * 512];
__device__ __align__(256) bf16 g_inwh[2 * 1024 * HID],  g_inwl[2 * 1024 * HID];
__device__ __align__(256) bf16 g_xpwh[2 * 48 * 512],    g_xpwl[2 * 48 * 512];

// ---------------- packed f32x2 helpers (SASS FFMA2 path, PTX-only) -------------
__device__ __forceinline__ float2 fma2(float2 a, float2 b, float2 c) {
    float2 r;
    asm("fma.rn.f32x2 %0, %1, %2, %3;"
        : "=l"(*reinterpret_cast<unsigned long long*>(&r))
        : "l"(*reinterpret_cast<unsigned long long*>(&a)),
          "l"(*reinterpret_cast<unsigned long long*>(&b)),
          "l"(*reinterpret_cast<unsigned long long*>(&c)));
    return r;
}
__device__ __forceinline__ float2 mul2(float2 a, float2 b) {
    float2 r;
    asm("mul.rn.f32x2 %0, %1, %2;"
        : "=l"(*reinterpret_cast<unsigned long long*>(&r))
        : "l"(*reinterpret_cast<unsigned long long*>(&a)),
          "l"(*reinterpret_cast<unsigned long long*>(&b)));
    return r;
}
__device__ __forceinline__ float ex2f(float x) {
    float r; asm("ex2.approx.f32 %0, %1;" : "=f"(r) : "f"(x)); return r;
}

// ---------------- fp32 -> bf16 (hi, lo) splits --------------------------------
__global__ void split_x(const float* __restrict__ src,
                        bf16* __restrict__ hi, bf16* __restrict__ lo, int n)
{
    int i = (blockIdx.x * blockDim.x + threadIdx.x) * 4;
    if (i >= n) return;
    float4 v = *(const float4*)(src + i);
    float vv[4] = {v.x, v.y, v.z, v.w};
#pragma unroll
    for (int j = 0; j < 4; j++) {
        bf16 h = __float2bfloat16(vv[j]);
        hi[i + j] = h;
        lo[i + j] = __float2bfloat16(vv[j] - __bfloat162float(h));
    }
}

__global__ void split_w(const float* __restrict__ w1, bf16* __restrict__ h1, bf16* __restrict__ l1, int n1,
                        const float* __restrict__ w2, bf16* __restrict__ h2, bf16* __restrict__ l2, int n2,
                        const float* __restrict__ w3, bf16* __restrict__ h3, bf16* __restrict__ l3, int n3)
{
    int i = (blockIdx.x * blockDim.x + threadIdx.x) * 4;
    const float* s; bf16 *ph, *pl; int off;
    if (i < n1)                { s = w1; ph = h1; pl = l1; off = i; }
    else if (i < n1 + n2)      { s = w2; ph = h2; pl = l2; off = i - n1; }
    else if (i < n1 + n2 + n3) { s = w3; ph = h3; pl = l3; off = i - n1 - n2; }
    else return;
    float4 v = *(const float4*)(s + off);
    float vv[4] = {v.x, v.y, v.z, v.w};
#pragma unroll
    for (int j = 0; j < 4; j++) {
        bf16 h = __float2bfloat16(vv[j]);
        ph[off + j] = h;
        pl[off + j] = __float2bfloat16(vv[j] - __bfloat162float(h));
    }
}

// =================== bf16 tensor-core GEMM (3-term split), BK=32, 2-stage ======
// C[M,N] = A[M,K] @ W[N,K]^T (+bias), operands as bf16 (hi, lo) pairs.
// Product al*bh + ah*bl + ah*bh -> ~2^-17 relative error; fp32 accumulate.
// Block tile 128 x (64*NJ) x 32; 256 threads = 8 warps in 2(m) x 4(n).

static constexpr int BK   = 32;
static constexpr int LDT  = 40;   // bf16 elems per smem row (80B); LDSM conflict-free
static constexpr int NSTG = 2;

__device__ __forceinline__ void cp16(void* dst, const void* src, int srcbytes) {
    unsigned int d = (unsigned int)__cvta_generic_to_shared(dst);
    asm volatile("cp.async.cg.shared.global [%0], [%1], 16, %2;\n"
                 :: "r"(d), "l"(src), "r"(srcbytes));
}
__device__ __forceinline__ void cp_commit() {
    asm volatile("cp.async.commit_group;\n");
}
template<int Nleft>
__device__ __forceinline__ void cp_wait() {
    asm volatile("cp.async.wait_group %0;\n" :: "n"(Nleft));
}

template<int NJ, bool GUARD, bool OUTSPLIT>
__global__ void __launch_bounds__(256)
gemm_bf(const bf16* __restrict__ Ah, const bf16* __restrict__ Al, long sA,
        const bf16* __restrict__ Bh, const bf16* __restrict__ Bl, long sB,
        float* __restrict__ C, bf16* __restrict__ Chi, bf16* __restrict__ Clo, long sC,
        const float* __restrict__ bias,
        int M, int N, int K)
{
    constexpr int BN  = 64 * NJ;
    constexpr int A_T = 128 * LDT;           // bf16 elems per A tile (5120)
    constexpr int B_T = BN * LDT;
    constexpr int STG = 2 * A_T + 2 * B_T;   // hi + lo
    constexpr int LDCs = BN + 4;
    extern __shared__ bf16 smb[];
    float* smf = reinterpret_cast<float*>(smb);   // epilogue/bias alias

    const int t = threadIdx.x;
    const int wid = t >> 5;
    const int wm = wid & 1;        // 0..1  (64-row slab)
    const int wn = wid >> 1;       // 0..3  (16*NJ-col slab)
    const long m0 = (long)blockIdx.y * 128;
    const int  n0 = blockIdx.x * BN;
    Ah += (long)blockIdx.z * sA;  Al += (long)blockIdx.z * sA;
    Bh += (long)blockIdx.z * sB;  Bl += (long)blockIdx.z * sB;
    if (C)   C   += (long)blockIdx.z * sC;
    if (Chi) { Chi += (long)blockIdx.z * sC; Clo += (long)blockIdx.z * sC; }

    // cp.async mapping: thread -> row t>>2 (0..63), col (t&3)*8 within 32-col chunk
    const int r4 = t >> 2;
    const int c4 = (t & 3) * 8;
    const bf16* Ahg0 = Ah + (m0 + r4) * (long)K + c4;
    const bf16* Alg0 = Al + (m0 + r4) * (long)K + c4;
    const bf16* Ahg1 = Ahg0 + 64 * (long)K;
    const bf16* Alg1 = Alg0 + 64 * (long)K;
    // B rows: NJ==2 -> rows r4 and r4+64; NJ==1 -> rows r4 only
    const int bn0 = n0 + r4;
    const int bn1 = n0 + r4 + 64;
    const int bnc0 = GUARD ? (bn0 < N ? bn0 : 0) : bn0;
    const bf16* Bhg0 = Bh + (long)bnc0 * K + c4;
    const bf16* Blg0 = Bl + (long)bnc0 * K + c4;
    const bf16* Bhg1 = Bh + (long)bn1 * K + c4;   // only used when NJ==2 (no guard)
    const bf16* Blg1 = Bl + (long)bn1 * K + c4;
    const int  bb0 = (!GUARD || bn0 < N) ? 16 : 0;

    wmma::fragment<wmma::accumulator, 16, 16, 16, float> acc[4][NJ];

    // ---- bias -> accumulator init ----
    if (bias) {
        if (t < BN) {
            float v = (!GUARD || (n0 + t) < N) ? bias[n0 + t] : 0.f;
#pragma unroll
            for (int r = 0; r < 16; r++) smf[r * LDCs + t] = v;
        }
        __syncthreads();
        wmma::fragment<wmma::accumulator, 16, 16, 16, float> bf;
#pragma unroll
        for (int j = 0; j < NJ; j++) {
            wmma::load_matrix_sync(bf, smf + wn * 16 * NJ + j * 16, LDCs, wmma::mem_row_major);
#pragma unroll
            for (int i = 0; i < 4; i++)
#pragma unroll
                for (int e = 0; e < bf.num_elements; e++) acc[i][j].x[e] = bf.x[e];
        }
        __syncthreads();
    } else {
#pragma unroll
        for (int i = 0; i < 4; i++)
#pragma unroll
            for (int j = 0; j < NJ; j++) wmma::fill_fragment(acc[i][j], 0.f);
    }

    auto issue = [&](int s, int k) {
        bf16* st = smb + (size_t)s * STG;
        cp16(st + r4 * LDT + c4,               Ahg0 + k, 16);
        cp16(st + (r4 + 64) * LDT + c4,        Ahg1 + k, 16);
        cp16(st + A_T + r4 * LDT + c4,         Alg0 + k, 16);
        cp16(st + A_T + (r4 + 64) * LDT + c4,  Alg1 + k, 16);
        bf16* bs = st + 2 * A_T;
        cp16(bs + r4 * LDT + c4,       Bhg0 + k, bb0);
        cp16(bs + B_T + r4 * LDT + c4, Blg0 + k, bb0);
        if (NJ == 2) {
            cp16(bs + (r4 + 64) * LDT + c4,       Bhg1 + k, 16);
            cp16(bs + B_T + (r4 + 64) * LDT + c4, Blg1 + k, 16);
        }
    };

    // prologue: stage 0
    issue(0, 0);
    cp_commit();

    int s = 0;
    for (int k0 = 0; k0 < K; k0 += BK) {
        cp_wait<0>();
        __syncthreads();
        // prefetch next stage while computing current (async, disjoint buffer)
        if (k0 + BK < K) issue(s ^ 1, k0 + BK);
        cp_commit();

        bf16* st = smb + (size_t)s * STG;
#pragma unroll
        for (int kk = 0; kk < BK; kk += 16) {
            wmma::fragment<wmma::matrix_a, 16, 16, 16, bf16, wmma::row_major> ah[4], al[4];
            wmma::fragment<wmma::matrix_b, 16, 16, 16, bf16, wmma::col_major> bh[NJ], bl[NJ];
#pragma unroll
            for (int i = 0; i < 4; i++) {
                int r = wm * 64 + i * 16;
                wmma::load_matrix_sync(ah[i], st + r * LDT + kk, LDT);
                wmma::load_matrix_sync(al[i], st + A_T + r * LDT + kk, LDT);
            }
#pragma unroll
            for (int j = 0; j < NJ; j++) {
                int c = wn * 16 * NJ + j * 16;
                wmma::load_matrix_sync(bh[j], st + 2 * A_T + c * LDT + kk, LDT);
                wmma::load_matrix_sync(bl[j], st + 2 * A_T + B_T + c * LDT + kk, LDT);
            }
#pragma unroll
            for (int i = 0; i < 4; i++)
#pragma unroll
                for (int j = 0; j < NJ; j++) {
                    wmma::mma_sync(acc[i][j], al[i], bh[j], acc[i][j]);
                    wmma::mma_sync(acc[i][j], ah[i], bl[j], acc[i][j]);
                    wmma::mma_sync(acc[i][j], ah[i], bh[j], acc[i][j]);
                }
        }
        s ^= 1;
    }

    // ---- epilogue ----
    if (OUTSPLIT) {
        __syncthreads();
#pragma unroll
        for (int i = 0; i < 4; i++)
#pragma unroll
            for (int j = 0; j < NJ; j++)
                wmma::store_matrix_sync(smf + (wm * 64 + i * 16) * LDCs + wn * 16 * NJ + j * 16,
                                        acc[i][j], LDCs, wmma::mem_row_major);
        __syncthreads();
        for (int e = t; e < 128 * BN; e += 256) {
            int r = e / BN, cn = e % BN;
            float v = smf[r * LDCs + cn];
            bf16 h = __float2bfloat16(v);
            long o = (m0 + r) * (long)N + n0 + cn;
            Chi[o] = h;
            Clo[o] = __float2bfloat16(v - __bfloat162float(h));
        }
    } else if (!GUARD) {
#pragma unroll
        for (int i = 0; i < 4; i++)
#pragma unroll
            for (int j = 0; j < NJ; j++)
                wmma::store_matrix_sync(
                    C + (m0 + wm * 64 + i * 16) * (long)N + n0 + wn * 16 * NJ + j * 16,
                    acc[i][j], N, wmma::mem_row_major);
    } else {
        __syncthreads();
        for (int half = 0; half < 2; half++) {
            if (wm == half) {
#pragma unroll
                for (int i = 0; i < 4; i++)
#pragma unroll
                    for (int j = 0; j < NJ; j++)
                        wmma::store_matrix_sync(smf + (i * 16) * LDCs + wn * 16 * NJ + j * 16,
                                                acc[i][j], LDCs, wmma::mem_row_major);
            }
            __syncthreads();
            for (int e = t; e < 64 * BN; e += 256) {
                int r = e / BN, cn = e % BN;
                int n = n0 + cn;
                if (n < N)
                    C[(m0 + half * 64 + r) * (long)N + n] = smf[r * LDCs + cn];
            }
            __syncthreads();
        }
    }
}

// ---------------- depthwise causal conv (dir-aware) + silu -> u hi/lo ---------
__global__ void conv_silu_kernel(const float* __restrict__ cw, const float* __restrict__ cb)
{
    int t = blockIdx.x * blockDim.x + threadIdx.x;   // 2*B*L*DI = 2^23
    int d   = t & (DI - 1);
    int l   = (t >> 9) & (L_ - 1);
    int b   = (t >> 20) & 3;
    int dir = (t >> 22) & 1;
    const float* xi = g_xz + (size_t)dir * BL * 2 * DI;   // xi = first DI cols
    const float* w  = cw + (dir * DI + d) * 4;
    float acc = cb[dir * DI + d];
    if (dir == 0) {
#pragma unroll
        for (int k = 0; k < 4; k++) {
            int ll = l - 3 + k;
            if (ll >= 0) acc = fmaf(w[k], xi[((size_t)b * L_ + ll) * (2 * DI) + d], acc);
        }
    } else {
#pragma unroll
        for (int k = 0; k < 4; k++) {
            int ll = l + 3 - k;
            if (ll < L_) acc = fmaf(w[k], xi[((size_t)b * L_ + ll) * (2 * DI) + d], acc);
        }
    }
    float uvv = acc / (1.f + __expf(-acc));   // silu
    size_t o = (size_t)dir * BL * DI + ((size_t)b * L_ + l) * DI + d;
    bf16 h = __float2bfloat16(uvv);
    g_uh[o] = h;
    g_ul[o] = __float2bfloat16(uvv - __bfloat162float(h));
}

// ---------------- chunked selective scan, pass 1 (dt fused; f32x2 packed) -----
__global__ void __launch_bounds__(128)
scan1_kernel(const float* __restrict__ A_log, const float* __restrict__ Dp,
             const float* __restrict__ dt_w, const float* __restrict__ dt_b)
{
    int bid = blockIdx.x;                 // 2048 = 2*4*64*4
    int dq  = bid & 3;
    int c   = (bid >> 2) & (NCH - 1);
    int b   = (bid >> 8) & 3;
    int dir = bid >> 10;
    int d   = dq * 128 + threadIdx.x;

    const bf16*  uhp = g_uh  + (size_t)dir * BL * DI;
    const bf16*  ulp = g_ul  + (size_t)dir * BL * DI;
    const float* zp  = g_xz  + (size_t)dir * BL * 2 * DI + DI;   // z half
    const float* dbp = g_dbc + (size_t)dir * BL * 48;

    // a2 has log2(e) folded in: dA = ex2(dt * a2)
    const float L2E = 1.4426950408889634f;
    float2 a2[NS / 2];
#pragma unroll
    for (int i = 0; i < NS / 2; i++) {
        const float* ap = A_log + (size_t)(dir * DI + d) * NS + 2 * i;
        a2[i] = make_float2(-__expf(ap[0]) * L2E, -__expf(ap[1]) * L2E);
    }
    const float Dv = Dp[dir * DI + d];

    float2 w2[RK / 2];
    {
        const float* wr = dt_w + (size_t)(dir * DI + d) * RK;
#pragma unroll
        for (int i = 0; i < RK / 2; i++) w2[i] = make_float2(wr[2 * i], wr[2 * i + 1]);
    }
    const float bb = dt_b[dir * DI + d];

    float2 h2[NS / 2], pp2[NS / 2], Kk2[NS / 2];
#pragma unroll
    for (int i = 0; i < NS / 2; i++) {
        h2[i] = make_float2(0.f, 0.f);
        pp2[i] = make_float2(1.f, 1.f);
        Kk2[i] = make_float2(0.f, 0.f);
    }
    float accl = 0.f;

    for (int j = 0; j < LC; j++) {
        int ss = c * LC + j;
        int l = dir ? (L_ - 1 - ss) : ss;
        size_t base = (size_t)b * L_ + l;
        float uv = __bfloat162float(uhp[base * DI + d]) + __bfloat162float(ulp[base * DI + d]);
        float zv = zp[base * 2 * DI + d];
        float gate = zv / (1.f + __expf(-zv));

        const float4* rr = (const float4*)(dbp + base * 48);
        float4 p0 = rr[0], p1 = rr[1], p2 = rr[2], p3 = rr[3];   // dt_lr
        // dt = softplus(dot(dt_lr, w) + bb) via packed fma
        float2 s2 = make_float2(bb, 0.f);
        s2 = fma2(make_float2(p0.x, p0.y), w2[0], s2);
        s2 = fma2(make_float2(p0.z, p0.w), w2[1], s2);
        s2 = fma2(make_float2(p1.x, p1.y), w2[2], s2);
        s2 = fma2(make_float2(p1.z, p1.w), w2[3], s2);
        s2 = fma2(make_float2(p2.x, p2.y), w2[4], s2);
        s2 = fma2(make_float2(p2.z, p2.w), w2[5], s2);
        s2 = fma2(make_float2(p3.x, p3.y), w2[6], s2);
        s2 = fma2(make_float2(p3.z, p3.w), w2[7], s2);
        float sdt = s2.x + s2.y;
        float dtv = (sdt > 15.f) ? sdt : log1pf(__expf(sdt));
        float x = dtv * uv;

        float4 q0 = rr[4], q1 = rr[5], q2 = rr[6], q3 = rr[7];   // B
        float4 q4 = rr[8], q5 = rr[9], q6 = rr[10], q7 = rr[11]; // C
        float2 Bv[8] = {{q0.x, q0.y}, {q0.z, q0.w}, {q1.x, q1.y}, {q1.z, q1.w},
                        {q2.x, q2.y}, {q2.z, q2.w}, {q3.x, q3.y}, {q3.z, q3.w}};
        float2 Cv[8] = {{q4.x, q4.y}, {q4.z, q4.w}, {q5.x, q5.y}, {q5.z, q5.w},
                        {q6.x, q6.y}, {q6.z, q6.w}, {q7.x, q7.y}, {q7.z, q7.w}};

        float2 dt2 = make_float2(dtv, dtv);
        float2 x2  = make_float2(x, x);
        float2 g2  = make_float2(gate, gate);
        float2 y2  = make_float2(0.f, 0.f);
#pragma unroll
        for (int i = 0; i < NS / 2; i++) {
            float2 m = mul2(dt2, a2[i]);
            float2 dA = make_float2(ex2f(m.x), ex2f(m.y));
            h2[i]  = fma2(dA, h2[i], mul2(x2, Bv[i]));
            pp2[i] = mul2(pp2[i], dA);
            y2     = fma2(h2[i], Cv[i], y2);
            Kk2[i] = fma2(mul2(g2, Cv[i]), pp2[i], Kk2[i]);
        }
        accl = fmaf(gate, fmaf(uv, Dv, y2.x + y2.y), accl);
    }

    size_t r = (((size_t)dir * NCH + c) * B_ + b) * DI + d;
    g_al[r] = accl;
#pragma unroll
    for (int i = 0; i < NS / 2; i++) {
        *(float2*)&g_S [r * NS + 2 * i] = h2[i];
        *(float2*)&g_P [r * NS + 2 * i] = pp2[i];
        *(float2*)&g_Kc[r * NS + 2 * i] = Kk2[i];
    }
}

// ---------------- scan combine: 16 lanes per (dir,b,d), shuffle-reduce --------
__global__ void scan2_kernel()
{
    int t = blockIdx.x * blockDim.x + threadIdx.x;   // 65536
    int n   = t & 15;
    int idx = t >> 4;        // 0..4095 = dir*2048 + b*512 + d
    int dir = idx >> 11;
    int b   = (idx >> 9) & 3;
    int d   = idx & (DI - 1);
    float hin = 0.f, acc = 0.f;
    for (int c = 0; c < NCH; c++) {
        size_t r = (((size_t)dir * NCH + c) * B_ + b) * DI + d;
        if (n == 0) acc += g_al[r];
        acc = fmaf(hin, g_Kc[r * NS + n], acc);
        hin = fmaf(g_P[r * NS + n], hin, g_S[r * NS + n]);
    }
#pragma unroll
    for (int o = 8; o; o >>= 1) acc += __shfl_down_sync(0xffffffffu, acc, o, 16);
    if (n == 0) g_pool[idx] = acc;
}

// ---------------- head: pooled @ out_w^T (per dir) -> embd --------------------
__global__ void head1_kernel(const float* __restrict__ out_w)
{
    int idx = blockIdx.x * blockDim.x + threadIdx.x;   // B * 512 = 2048
    if (idx >= B_ * 2 * HID) return;
    int b = idx >> 9;
    int cf = idx & 511;
    int dir = cf >> 8;
    int cc = cf & (HID - 1);
    const float* pr = g_pool + dir * B_ * DI + b * DI;
    const float* wr = out_w + ((size_t)dir * HID + cc) * DI;
    float s = 0.f;
#pragma unroll 8
    for (int k = 0; k < DI; k++) s = fmaf(pr[k], wr[k], s);
    g_embd[b * 512 + cf] = s * (1.f / (float)L_);
}

// ---------------- head: embd @ op_w^T + op_b ----------------------------------
__global__ void head2_kernel(const float* __restrict__ op_w, const float* __restrict__ op_b,
                             float* __restrict__ out)
{
    int idx = blockIdx.x * blockDim.x + threadIdx.x;   // B * 256 = 1024
    if (idx >= B_ * HID) return;
    int b = idx >> 8;
    int m = idx & (HID - 1);
    const float* e = g_embd + b * 512;
    const float* w = op_w + (size_t)m * 512;
    float s = op_b[m];
#pragma unroll 8
    for (int c = 0; c < 512; c++) s = fmaf(e[c], w[c], s);
    out[b * HID + m] = s;
}

// ------------------------------------------------------------------------------
extern "C" void kernel_launch(void* const* d_in, const int* in_sizes, int n_in,
                              void* d_out, int out_size)
{
    const float* x      = (const float*)d_in[0];
    const float* ip_w   = (const float*)d_in[1];
    const float* ip_b   = (const float*)d_in[2];
    const float* in_w   = (const float*)d_in[3];
    const float* conv_w = (const float*)d_in[4];
    const float* conv_b = (const float*)d_in[5];
    const float* xproj_w= (const float*)d_in[6];
    const float* dt_w   = (const float*)d_in[7];
    const float* dt_b   = (const float*)d_in[8];
    const float* A_log  = (const float*)d_in[9];
    const float* Dp     = (const float*)d_in[10];
    const float* out_w  = (const float*)d_in[11];
    const float* op_w   = (const float*)d_in[12];
    const float* op_b   = (const float*)d_in[13];
    float* out = (float*)d_out;

    float *pxz, *pdbc;
    bf16 *pxh, *pxl, *phh, *phl, *puh, *pul, *pipwh, *pipwl, *pinwh, *pinwl, *pxpwh, *pxpwl;
    cudaGetSymbolAddress((void**)&pxz,   g_xz);
    cudaGetSymbolAddress((void**)&pdbc,  g_dbc);
    cudaGetSymbolAddress((void**)&pxh,   g_xh);
    cudaGetSymbolAddress((void**)&pxl,   g_xl);
    cudaGetSymbolAddress((void**)&phh,   g_hh);
    cudaGetSymbolAddress((void**)&phl,   g_hl);
    cudaGetSymbolAddress((void**)&puh,   g_uh);
    cudaGetSymbolAddress((void**)&pul,   g_ul);
    cudaGetSymbolAddress((void**)&pipwh, g_ipwh);
    cudaGetSymbolAddress((void**)&pipwl, g_ipwl);
    cudaGetSymbolAddress((void**)&pinwh, g_inwh);
    cudaGetSymbolAddress((void**)&pinwl, g_inwl);
    cudaGetSymbolAddress((void**)&pxpwh, g_xpwh);
    cudaGetSymbolAddress((void**)&pxpwl, g_xpwl);

    // dynamic smem: 2 stages * (2*A_T + 2*B_T) bf16
    const int smem1 = NSTG * (2 * 128 * LDT + 2 * 64 * LDT) * (int)sizeof(bf16);   // 61440
    const int smem2 = NSTG * (2 * 128 * LDT + 2 * 128 * LDT) * (int)sizeof(bf16);  // 81920
    cudaFuncSetAttribute(gemm_bf<1, false, true>,  cudaFuncAttributeMaxDynamicSharedMemorySize, smem1);
    cudaFuncSetAttribute(gemm_bf<2, false, false>, cudaFuncAttributeMaxDynamicSharedMemorySize, smem2);
    cudaFuncSetAttribute(gemm_bf<1, true, false>,  cudaFuncAttributeMaxDynamicSharedMemorySize, smem1);

    dim3 blk(256);
    const int n1 = HID * 512, n2 = 2 * 1024 * HID, n3 = 2 * 48 * 512;

    // 1) split x -> bf16 hi/lo
    split_x<<<(BL * 512 / 4 + 255) / 256, 256>>>(x, pxh, pxl, BL * 512);
    // 2) split all weights (one launch)
    split_w<<<((n1 + n2 + n3) / 4 + 255) / 256, 256>>>(
        ip_w, pipwh, pipwl, n1, in_w, pinwh, pinwl, n2, xproj_w, pxpwh, pxpwl, n3);
    // 3) h = x @ ip_w^T + ip_b -> bf16 hi/lo directly   [8192,512]x[256,512]
    gemm_bf<1, false, true><<<dim3(HID / 64, BL / 128, 1), blk, smem1>>>(
        pxh, pxl, 0, pipwh, pipwl, 0, nullptr, phh, phl, 0, ip_b, BL, HID, 512);
    // 4) xz_dir = h @ in_w[dir]^T   [8192,256]x[1024,256] -> [8192,1024] x2  (PROFILED)
    gemm_bf<2, false, false><<<dim3(1024 / 128, BL / 128, 2), blk, smem2>>>(
        phh, phl, 0, pinwh, pinwl, (long)1024 * HID, pxz, nullptr, nullptr, (long)BL * 1024,
        nullptr, BL, 1024, HID);
    // 5) u = silu(depthwise causal conv(xi) + cb) -> bf16 hi/lo
    conv_silu_kernel<<<(2 * BL * DI) / 256, 256>>>(conv_w, conv_b);
    // 6) dbc = u @ xproj_w[dir]^T   [8192,512]x[48,512] -> [8192,48] x2
    gemm_bf<1, true, false><<<dim3(1, BL / 128, 2), blk, smem1>>>(
        puh, pul, (long)BL * DI, pxpwh, pxpwl, (long)48 * 512, pdbc, nullptr, nullptr,
        (long)BL * 48, nullptr, BL, 48, 512);
    // 7) chunked scan pass 1 (dt fused; f32x2-packed state recurrences)
    scan1_kernel<<<2048, 128>>>(A_log, Dp, dt_w, dt_b);
    // 8) chunk combine -> pooled sums
    scan2_kernel<<<256, 256>>>();
    // 9) pooled @ out_w^T (mean folded), concat dirs -> embd
    head1_kernel<<<8, 256>>>(out_w);
    // 10) embd @ op_w^T + op_b -> out
    head2_kernel<<<4, 256>>>(op_w, op_b, out);
}